// round 3
// baseline (speedup 1.0000x reference)
#include <cuda_runtime.h>
#include <cstdint>

#define T_ 128
#define B_ 512
#define D_ 768
#define R_ (T_*B_)   // 65536 rows

typedef unsigned long long ull;

// ---------------- scratch (static device globals; no allocation) ----------------
__device__ float g_xproj[R_ * 64];   // [r][64]: cols 0..31 fwd gates (i,f,g,o x8), 32..63 bwd; biases included
__device__ float g_h[R_ * 16];       // [t][b][16]: 0..7 fwd h, 8..15 bwd h
__device__ float g_zproj[R_ * 64];   // ptr-LSTM input projection (+bias)
__device__ float g_z[R_ * 16];       // ptr-LSTM hidden states

// ---------------- helpers ----------------
__device__ __forceinline__ ull ffma2(ull a, ull b, ull c) {
    ull d;
    asm("fma.rn.f32x2 %0, %1, %2, %3;" : "=l"(d) : "l"(a), "l"(b), "l"(c));
    return d;
}
__device__ __forceinline__ ull pack2(float lo, float hi) {
    ull r;
    asm("mov.b64 %0, {%1, %2};" : "=l"(r) : "f"(lo), "f"(hi));
    return r;
}
__device__ __forceinline__ float2 unpack2(ull v) {
    float lo, hi;
    asm("mov.b64 {%0, %1}, %2;" : "=f"(lo), "=f"(hi) : "l"(v));
    return make_float2(lo, hi);
}
__device__ __forceinline__ float sigm(float x) {
    return __fdividef(1.f, 1.f + __expf(-x));
}
__device__ __forceinline__ float tanh_f(float x) {
    // tanh(x) = 2*sigmoid(2x) - 1 ; abs err ~1e-7, fine at 1e-3 tolerance
    return __fmaf_rn(2.f, sigm(2.f * x), -1.f);
}

// ---------------- K1: input projection GEMM  C[R x 64] = X[R x 768] @ W^T + bias ----
// 256 rows x 64 cols per CTA, 256 threads, 8x8 micro-tile, f32x2 packed FMA.
// X tile stored k-major so adjacent rows form f32x2 pairs; W stored duplicated (w,w)
// with a swizzle so the 8 per-j LDS.64 are bank-conflict-free.
__global__ void __launch_bounds__(256) proj_kernel(
    const float* __restrict__ X,
    const float* __restrict__ Wf, const float* __restrict__ Wb,
    const float* __restrict__ bif, const float* __restrict__ bhf,
    const float* __restrict__ bib, const float* __restrict__ bhb)
{
    __shared__ __align__(16) float  xs[8][256];   // [kk][row]
    __shared__ __align__(16) float2 ws[8][64];    // [kk][swizzled col], duplicated (w,w)

    const int tid = threadIdx.x;
    const int ttx = tid & 7;        // col group: cols 8*ttx .. 8*ttx+7
    const int tty = tid >> 3;       // row group: rows 8*tty .. 8*tty+7
    const int row0 = blockIdx.x * 256;

    ull acc[4][8];
    #pragma unroll
    for (int i = 0; i < 4; i++)
        #pragma unroll
        for (int j = 0; j < 8; j++) acc[i][j] = 0ULL;

    const float* xrow = X + (size_t)(row0 + tid) * D_;

    for (int k0 = 0; k0 < D_; k0 += 8) {
        float4 v0 = *(const float4*)(xrow + k0);
        float4 v1 = *(const float4*)(xrow + k0 + 4);
        xs[0][tid] = v0.x; xs[1][tid] = v0.y; xs[2][tid] = v0.z; xs[3][tid] = v0.w;
        xs[4][tid] = v1.x; xs[5][tid] = v1.y; xs[6][tid] = v1.z; xs[7][tid] = v1.w;
        #pragma unroll
        for (int e0 = 0; e0 < 2; e0++) {
            int e  = tid + e0 * 256;         // 512 entries = 8 kk x 64 cols
            int kk = e >> 6, c = e & 63;
            float w = (c < 32) ? Wf[c * D_ + k0 + kk] : Wb[(c - 32) * D_ + k0 + kk];
            ws[kk][((c & 7) << 3) | (c >> 3)] = make_float2(w, w);  // swizzled store
        }
        __syncthreads();
        #pragma unroll
        for (int kk = 0; kk < 8; kk++) {
            const ull* ar = (const ull*)(&xs[kk][0]);
            const ull* br = (const ull*)(&ws[kk][0]);
            ull a0 = ar[tty * 4 + 0], a1 = ar[tty * 4 + 1];
            ull a2 = ar[tty * 4 + 2], a3 = ar[tty * 4 + 3];
            #pragma unroll
            for (int j = 0; j < 8; j++) {
                // col (8*ttx + j) lives at swizzled slot j*8 + ttx
                ull b = br[j * 8 + ttx];
                acc[0][j] = ffma2(a0, b, acc[0][j]);
                acc[1][j] = ffma2(a1, b, acc[1][j]);
                acc[2][j] = ffma2(a2, b, acc[2][j]);
                acc[3][j] = ffma2(a3, b, acc[3][j]);
            }
        }
        __syncthreads();
    }

    float bias[8];
    #pragma unroll
    for (int j = 0; j < 8; j++) {
        int c = ttx * 8 + j;
        bias[j] = (c < 32) ? (bif[c] + bhf[c]) : (bib[c - 32] + bhb[c - 32]);
    }
    #pragma unroll
    for (int i = 0; i < 4; i++) {
        int r0 = row0 + tty * 8 + 2 * i;
        float o0[8], o1[8];
        #pragma unroll
        for (int j = 0; j < 8; j++) {
            float2 v = unpack2(acc[i][j]);
            o0[j] = v.x + bias[j];
            o1[j] = v.y + bias[j];
        }
        float4* d0 = (float4*)(g_xproj + (size_t)r0 * 64 + ttx * 8);
        d0[0] = make_float4(o0[0], o0[1], o0[2], o0[3]);
        d0[1] = make_float4(o0[4], o0[5], o0[6], o0[7]);
        float4* d1 = (float4*)(g_xproj + (size_t)(r0 + 1) * 64 + ttx * 8);
        d1[0] = make_float4(o1[0], o1[1], o1[2], o1[3]);
        d1[1] = make_float4(o1[4], o1[5], o1[6], o1[7]);
    }
}

// ---------------- K2: bidirectional LSTM scan (H=8) ----------------
// grid (16, 2): blockIdx.y = direction. 256 threads = 32 batch elems x 8 units.
__global__ void __launch_bounds__(256) lstm_bi_kernel(
    const float* __restrict__ Whhf, const float* __restrict__ Whhb)
{
    __shared__ float Whh[32][9];   // padded: conflict-free
    const int tid = threadIdx.x;
    const int dir = blockIdx.y;
    {
        const float* W = dir ? Whhb : Whhf;
        Whh[tid >> 3][tid & 7] = W[tid];   // 32x8 = 256
    }
    __syncthreads();

    const int e = tid >> 3, u = tid & 7;
    const int b = blockIdx.x * 32 + e;
    const int base = tid & 24;             // lane group base for shfl (4 elems/warp)

    float hv[8];
    #pragma unroll
    for (int j = 0; j < 8; j++) hv[j] = 0.f;
    float cu = 0.f;

    const float* xp_base = g_xproj + dir * 32;
    int tt0 = dir ? (T_ - 1) : 0;
    const float* xp = xp_base + ((size_t)tt0 * B_ + b) * 64;
    float nxi = xp[u], nxf = xp[8 + u], nxg = xp[16 + u], nxo = xp[24 + u];

    float* hp0 = g_h + (size_t)b * 16 + dir * 8 + u;

    for (int s = 0; s < T_; s++) {
        const int tt = dir ? (T_ - 1 - s) : s;
        float xi = nxi, xf = nxf, xg = nxg, xo = nxo;
        if (s + 1 < T_) {
            int nt = dir ? (T_ - 2 - s) : (s + 1);
            const float* xpn = xp_base + ((size_t)nt * B_ + b) * 64;
            nxi = xpn[u]; nxf = xpn[8 + u]; nxg = xpn[16 + u]; nxo = xpn[24 + u];
        }
        float gi = xi, gf = xf, gg = xg, go = xo;
        #pragma unroll
        for (int j = 0; j < 8; j++) {
            float h = hv[j];
            gi = __fmaf_rn(Whh[u][j],      h, gi);
            gf = __fmaf_rn(Whh[8 + u][j],  h, gf);
            gg = __fmaf_rn(Whh[16 + u][j], h, gg);
            go = __fmaf_rn(Whh[24 + u][j], h, go);
        }
        float ii = sigm(gi), ff = sigm(gf), g2 = tanh_f(gg), oo = sigm(go);
        cu = __fmaf_rn(ff, cu, ii * g2);
        float hu = oo * tanh_f(cu);
        hp0[(size_t)tt * (B_ * 16)] = hu;
        #pragma unroll
        for (int j = 0; j < 8; j++)
            hv[j] = __shfl_sync(0xffffffffu, hu, base + j);
    }
}

// ---------------- K3: ptr-LSTM input projection  zproj = h @ Wih_p^T + bias -------
__global__ void __launch_bounds__(256) zproj_kernel(
    const float* __restrict__ Wihp, const float* __restrict__ bip,
    const float* __restrict__ bhp)
{
    __shared__ float W[64][16];
    __shared__ float bias[64];
    const int tid = threadIdx.x;
    #pragma unroll
    for (int i = tid; i < 1024; i += 256) W[i >> 4][i & 15] = Wihp[i];
    if (tid < 64) bias[tid] = bip[tid] + bhp[tid];
    __syncthreads();

    size_t r = (size_t)blockIdx.x * 256 + tid;
    const float4* h4 = (const float4*)(g_h + r * 16);
    float4 a0 = h4[0], a1 = h4[1], a2 = h4[2], a3 = h4[3];
    float hr[16] = {a0.x, a0.y, a0.z, a0.w, a1.x, a1.y, a1.z, a1.w,
                    a2.x, a2.y, a2.z, a2.w, a3.x, a3.y, a3.z, a3.w};
    float* out = g_zproj + r * 64;
    #pragma unroll
    for (int g0 = 0; g0 < 64; g0 += 4) {
        float o[4];
        #pragma unroll
        for (int q = 0; q < 4; q++) {
            int g = g0 + q;
            float a = bias[g];
            #pragma unroll
            for (int k = 0; k < 16; k++) a = __fmaf_rn(W[g][k], hr[k], a);
            o[q] = a;
        }
        *(float4*)(out + g0) = make_float4(o[0], o[1], o[2], o[3]);
    }
}

// ---------------- K4: ptr LSTM scan (H=16) ----------------
// 256 threads = 16 elems x 16 units; grid 32.
__global__ void __launch_bounds__(256) lstm_ptr_kernel(const float* __restrict__ Whhp)
{
    __shared__ float Whh[64][17];
    const int tid = threadIdx.x;
    #pragma unroll
    for (int i = tid; i < 1024; i += 256) Whh[i >> 4][i & 15] = Whhp[i];
    __syncthreads();

    const int e = tid >> 4, u = tid & 15;
    const int b = blockIdx.x * 16 + e;
    const int base = tid & 16;             // 2 elems per warp

    float hv[16];
    #pragma unroll
    for (int j = 0; j < 16; j++) hv[j] = 0.f;
    float cu = 0.f;

    const float* xp = g_zproj + (size_t)b * 64;
    float nxi = xp[u], nxf = xp[16 + u], nxg = xp[32 + u], nxo = xp[48 + u];
    float* zp0 = g_z + (size_t)b * 16 + u;

    for (int t = 0; t < T_; t++) {
        float xi = nxi, xf = nxf, xg = nxg, xo = nxo;
        if (t + 1 < T_) {
            const float* xpn = g_zproj + ((size_t)(t + 1) * B_ + b) * 64;
            nxi = xpn[u]; nxf = xpn[16 + u]; nxg = xpn[32 + u]; nxo = xpn[48 + u];
        }
        float gi = xi, gf = xf, gg = xg, go = xo;
        #pragma unroll
        for (int j = 0; j < 16; j++) {
            float h = hv[j];
            gi = __fmaf_rn(Whh[u][j],      h, gi);
            gf = __fmaf_rn(Whh[16 + u][j], h, gf);
            gg = __fmaf_rn(Whh[32 + u][j], h, gg);
            go = __fmaf_rn(Whh[48 + u][j], h, go);
        }
        float ii = sigm(gi), ff = sigm(gf), g2 = tanh_f(gg), oo = sigm(go);
        cu = __fmaf_rn(ff, cu, ii * g2);
        float hu = oo * tanh_f(cu);
        zp0[(size_t)t * (B_ * 16)] = hu;
        #pragma unroll
        for (int j = 0; j < 16; j++)
            hv[j] = __shfl_sync(0xffffffffu, hu, base + j);
    }
}

// ---------------- K5: fused attention + output head, one CTA per t ----------------
// pass1: thread c owns column c -> colsum_c = sum_b exp(h_b . z_c)  (no reduction)
// pass2: thread b owns row b    -> ctx_b = sum_c exp(h_b . z_c)/colsum_c * h_c
// then u = tanh(h W_h^T + ctx W_e^T), p = sigmoid(u . W_v). |S|<16 so no max needed.
#define ATT_SMEM_FLOATS (8192 + 8192 + 512 + 256 + 256 + 16)
__global__ void __launch_bounds__(512) attn_kernel(
    const float* __restrict__ W_h, const float* __restrict__ W_e,
    const float* __restrict__ W_v, float* __restrict__ out)
{
    extern __shared__ __align__(16) float sm[];
    float* hs   = sm;            // 512 x 16
    float* zs   = sm + 8192;     // 512 x 16
    float* cinv = sm + 16384;    // 512
    float* whs  = sm + 16896;    // 16 x 16
    float* wes  = sm + 17152;    // 16 x 16
    float* wvs  = sm + 17408;    // 16

    const int tid = threadIdx.x;
    const int t = blockIdx.x;
    {
        const float4* hsrc = (const float4*)(g_h + (size_t)t * (B_ * 16));
        const float4* zsrc = (const float4*)(g_z + (size_t)t * (B_ * 16));
        float4* hd = (float4*)hs;
        float4* zd = (float4*)zs;
        #pragma unroll
        for (int i = 0; i < 4; i++) {
            hd[tid + i * 512] = hsrc[tid + i * 512];
            zd[tid + i * 512] = zsrc[tid + i * 512];
        }
    }
    if (tid < 256) { whs[tid] = W_h[tid]; wes[tid] = W_e[tid]; }
    if (tid < 16)  wvs[tid] = W_v[tid];
    __syncthreads();

    // ---- pass 1 ----
    {
        const ulonglong2* zr = (const ulonglong2*)(zs + tid * 16);
        ulonglong2 zq0 = zr[0], zq1 = zr[1], zq2 = zr[2], zq3 = zr[3];
        float colsum = 0.f;
        #pragma unroll 2
        for (int bb = 0; bb < B_; bb++) {
            const ulonglong2* hr = (const ulonglong2*)(hs + bb * 16);
            ulonglong2 hq0 = hr[0], hq1 = hr[1], hq2 = hr[2], hq3 = hr[3];
            ull aA = 0ULL, aB = 0ULL;
            aA = ffma2(hq0.x, zq0.x, aA); aB = ffma2(hq0.y, zq0.y, aB);
            aA = ffma2(hq1.x, zq1.x, aA); aB = ffma2(hq1.y, zq1.y, aB);
            aA = ffma2(hq2.x, zq2.x, aA); aB = ffma2(hq2.y, zq2.y, aB);
            aA = ffma2(hq3.x, zq3.x, aA); aB = ffma2(hq3.y, zq3.y, aB);
            float2 va = unpack2(aA), vb = unpack2(aB);
            float S = (va.x + va.y) + (vb.x + vb.y);
            colsum += __expf(S);
        }
        cinv[tid] = __fdividef(1.f, colsum);
    }
    __syncthreads();

    // ---- pass 2 + output head ----
    {
        const ulonglong2* hrp = (const ulonglong2*)(hs + tid * 16);
        ulonglong2 hq0 = hrp[0], hq1 = hrp[1], hq2 = hrp[2], hq3 = hrp[3];
        ull cacc[8];
        #pragma unroll
        for (int k = 0; k < 8; k++) cacc[k] = 0ULL;

        #pragma unroll 2
        for (int c = 0; c < B_; c++) {
            const ulonglong2* zr = (const ulonglong2*)(zs + c * 16);
            ulonglong2 zq0 = zr[0], zq1 = zr[1], zq2 = zr[2], zq3 = zr[3];
            ull aA = 0ULL, aB = 0ULL;
            aA = ffma2(hq0.x, zq0.x, aA); aB = ffma2(hq0.y, zq0.y, aB);
            aA = ffma2(hq1.x, zq1.x, aA); aB = ffma2(hq1.y, zq1.y, aB);
            aA = ffma2(hq2.x, zq2.x, aA); aB = ffma2(hq2.y, zq2.y, aB);
            aA = ffma2(hq3.x, zq3.x, aA); aB = ffma2(hq3.y, zq3.y, aB);
            float2 va = unpack2(aA), vb = unpack2(aB);
            float S = (va.x + va.y) + (vb.x + vb.y);
            float w = __expf(S) * cinv[c];
            ull w2 = pack2(w, w);
            const ulonglong2* hc = (const ulonglong2*)(hs + c * 16);
            ulonglong2 hcq0 = hc[0], hcq1 = hc[1], hcq2 = hc[2], hcq3 = hc[3];
            cacc[0] = ffma2(hcq0.x, w2, cacc[0]); cacc[1] = ffma2(hcq0.y, w2, cacc[1]);
            cacc[2] = ffma2(hcq1.x, w2, cacc[2]); cacc[3] = ffma2(hcq1.y, w2, cacc[3]);
            cacc[4] = ffma2(hcq2.x, w2, cacc[4]); cacc[5] = ffma2(hcq2.y, w2, cacc[5]);
            cacc[6] = ffma2(hcq3.x, w2, cacc[6]); cacc[7] = ffma2(hcq3.y, w2, cacc[7]);
        }

        float ctxv[16], hbv[16];
        #pragma unroll
        for (int k = 0; k < 8; k++) {
            float2 v = unpack2(cacc[k]);
            ctxv[2 * k] = v.x; ctxv[2 * k + 1] = v.y;
        }
        {
            float2 v;
            v = unpack2(hq0.x); hbv[0] = v.x;  hbv[1] = v.y;
            v = unpack2(hq0.y); hbv[2] = v.x;  hbv[3] = v.y;
            v = unpack2(hq1.x); hbv[4] = v.x;  hbv[5] = v.y;
            v = unpack2(hq1.y); hbv[6] = v.x;  hbv[7] = v.y;
            v = unpack2(hq2.x); hbv[8] = v.x;  hbv[9] = v.y;
            v = unpack2(hq2.y); hbv[10] = v.x; hbv[11] = v.y;
            v = unpack2(hq3.x); hbv[12] = v.x; hbv[13] = v.y;
            v = unpack2(hq3.y); hbv[14] = v.x; hbv[15] = v.y;
        }
        float pacc = 0.f;
        #pragma unroll
        for (int d = 0; d < 16; d++) {
            float a = 0.f;
            #pragma unroll
            for (int k = 0; k < 16; k++) a = __fmaf_rn(whs[d * 16 + k], hbv[k], a);
            #pragma unroll
            for (int k = 0; k < 16; k++) a = __fmaf_rn(wes[d * 16 + k], ctxv[k], a);
            float ud = tanh_f(a);
            pacc = __fmaf_rn(ud, wvs[d], pacc);
        }
        out[(size_t)t * B_ + tid] = sigm(pacc);
    }
}

// ---------------- launch ----------------
extern "C" void kernel_launch(void* const* d_in, const int* in_sizes, int n_in,
                              void* d_out, int out_size)
{
    (void)in_sizes; (void)n_in; (void)out_size;
    const float* X     = (const float*)d_in[0];
    const float* Wih_f = (const float*)d_in[1];
    const float* Whh_f = (const float*)d_in[2];
    const float* bih_f = (const float*)d_in[3];
    const float* bhh_f = (const float*)d_in[4];
    const float* Wih_b = (const float*)d_in[5];
    const float* Whh_b = (const float*)d_in[6];
    const float* bih_b = (const float*)d_in[7];
    const float* bhh_b = (const float*)d_in[8];
    const float* Wih_p = (const float*)d_in[9];
    const float* Whh_p = (const float*)d_in[10];
    const float* bih_p = (const float*)d_in[11];
    const float* bhh_p = (const float*)d_in[12];
    const float* W_h   = (const float*)d_in[13];
    const float* W_e   = (const float*)d_in[14];
    const float* W_v   = (const float*)d_in[15];
    float* out = (float*)d_out;

    proj_kernel<<<256, 256>>>(X, Wih_f, Wih_b, bih_f, bhh_f, bih_b, bhh_b);
    lstm_bi_kernel<<<dim3(16, 2), 256>>>(Whh_f, Whh_b);
    zproj_kernel<<<256, 256>>>(Wih_p, bih_p, bhh_p);
    lstm_ptr_kernel<<<32, 256>>>(Whh_p);

    const int att_smem = ATT_SMEM_FLOATS * (int)sizeof(float);  // ~69.7 KB
    cudaFuncSetAttribute(attn_kernel, cudaFuncAttributeMaxDynamicSharedMemorySize, att_smem);
    attn_kernel<<<128, 512, att_smem>>>(W_h, W_e, W_v, out);
}

// round 4
// speedup vs baseline: 1.0508x; 1.0508x over previous
#include <cuda_runtime.h>
#include <cstdint>

#define T_ 128
#define B_ 512
#define D_ 768
#define R_ (T_*B_)   // 65536 rows

typedef unsigned long long ull;

// ---------------- scratch (static device globals; no allocation) ----------------
// Gate-interleaved layouts: one float4 per (element, unit) per step.
__device__ __align__(16) float g_xproj[R_ * 64];  // [t][b][dir][u][4] : col = dir*32 + u*4 + gate
__device__ __align__(16) float g_h[R_ * 16];      // [t][b][16]: 0..7 fwd h, 8..15 bwd h
__device__ __align__(16) float g_zproj[R_ * 64];  // [t][b][u][4]     : col = u*4 + gate
__device__ __align__(16) float g_z[R_ * 16];      // ptr-LSTM hidden states

// ---------------- helpers ----------------
__device__ __forceinline__ ull ffma2(ull a, ull b, ull c) {
    ull d;
    asm("fma.rn.f32x2 %0, %1, %2, %3;" : "=l"(d) : "l"(a), "l"(b), "l"(c));
    return d;
}
__device__ __forceinline__ ull pack2(float lo, float hi) {
    ull r;
    asm("mov.b64 %0, {%1, %2};" : "=l"(r) : "f"(lo), "f"(hi));
    return r;
}
__device__ __forceinline__ float2 unpack2(ull v) {
    float lo, hi;
    asm("mov.b64 {%0, %1}, %2;" : "=f"(lo), "=f"(hi) : "l"(v));
    return make_float2(lo, hi);
}
__device__ __forceinline__ float sigm(float x) {
    return __fdividef(1.f, 1.f + __expf(-x));
}
__device__ __forceinline__ float tanh_f(float x) {
    return __fmaf_rn(2.f, sigm(2.f * x), -1.f);
}

// map output column c (0..63) of the big projection to the original W row.
// new layout: dir = c>>5, u = (c&31)>>2, gate = (c&31)&3 ; orig row = gate*8 + u
__device__ __forceinline__ int bi_row_of_col(int c, int& dir) {
    dir = c >> 5;
    int w = c & 31;
    return (w & 3) * 8 + (w >> 2);
}

// ---------------- K1: input projection GEMM  C[R x 64] = X[R x 768] @ W^T + bias ----
__global__ void __launch_bounds__(256) proj_kernel(
    const float* __restrict__ X,
    const float* __restrict__ Wf, const float* __restrict__ Wb,
    const float* __restrict__ bif, const float* __restrict__ bhf,
    const float* __restrict__ bib, const float* __restrict__ bhb)
{
    __shared__ __align__(16) float  xs[8][256];   // [kk][row]
    __shared__ __align__(16) float2 ws[8][64];    // [kk][swizzled col], duplicated (w,w)

    const int tid = threadIdx.x;
    const int ttx = tid & 7;        // col group: cols 8*ttx .. 8*ttx+7
    const int tty = tid >> 3;       // row group: rows 8*tty .. 8*tty+7
    const int row0 = blockIdx.x * 256;

    ull acc[4][8];
    #pragma unroll
    for (int i = 0; i < 4; i++)
        #pragma unroll
        for (int j = 0; j < 8; j++) acc[i][j] = 0ULL;

    const float* xrow = X + (size_t)(row0 + tid) * D_;

    for (int k0 = 0; k0 < D_; k0 += 8) {
        float4 v0 = *(const float4*)(xrow + k0);
        float4 v1 = *(const float4*)(xrow + k0 + 4);
        xs[0][tid] = v0.x; xs[1][tid] = v0.y; xs[2][tid] = v0.z; xs[3][tid] = v0.w;
        xs[4][tid] = v1.x; xs[5][tid] = v1.y; xs[6][tid] = v1.z; xs[7][tid] = v1.w;
        #pragma unroll
        for (int e0 = 0; e0 < 2; e0++) {
            int e  = tid + e0 * 256;         // 512 entries = 8 kk x 64 cols
            int kk = e >> 6, c = e & 63;
            int dir;
            int r = bi_row_of_col(c, dir);   // permuted: col c <- W row r of dir
            float w = dir ? Wb[r * D_ + k0 + kk] : Wf[r * D_ + k0 + kk];
            ws[kk][((c & 7) << 3) | (c >> 3)] = make_float2(w, w);  // swizzled store
        }
        __syncthreads();
        #pragma unroll
        for (int kk = 0; kk < 8; kk++) {
            const ull* ar = (const ull*)(&xs[kk][0]);
            const ull* br = (const ull*)(&ws[kk][0]);
            ull a0 = ar[tty * 4 + 0], a1 = ar[tty * 4 + 1];
            ull a2 = ar[tty * 4 + 2], a3 = ar[tty * 4 + 3];
            #pragma unroll
            for (int j = 0; j < 8; j++) {
                ull b = br[j * 8 + ttx];
                acc[0][j] = ffma2(a0, b, acc[0][j]);
                acc[1][j] = ffma2(a1, b, acc[1][j]);
                acc[2][j] = ffma2(a2, b, acc[2][j]);
                acc[3][j] = ffma2(a3, b, acc[3][j]);
            }
        }
        __syncthreads();
    }

    float bias[8];
    #pragma unroll
    for (int j = 0; j < 8; j++) {
        int c = ttx * 8 + j;
        int dir;
        int r = bi_row_of_col(c, dir);
        bias[j] = dir ? (bib[r] + bhb[r]) : (bif[r] + bhf[r]);
    }
    #pragma unroll
    for (int i = 0; i < 4; i++) {
        int r0 = row0 + tty * 8 + 2 * i;
        float o0[8], o1[8];
        #pragma unroll
        for (int j = 0; j < 8; j++) {
            float2 v = unpack2(acc[i][j]);
            o0[j] = v.x + bias[j];
            o1[j] = v.y + bias[j];
        }
        float4* d0 = (float4*)(g_xproj + (size_t)r0 * 64 + ttx * 8);
        d0[0] = make_float4(o0[0], o0[1], o0[2], o0[3]);
        d0[1] = make_float4(o0[4], o0[5], o0[6], o0[7]);
        float4* d1 = (float4*)(g_xproj + (size_t)(r0 + 1) * 64 + ttx * 8);
        d1[0] = make_float4(o1[0], o1[1], o1[2], o1[3]);
        d1[1] = make_float4(o1[4], o1[5], o1[6], o1[7]);
    }
}

// ---------------- K2: bidirectional LSTM scan (H=8) ----------------
// grid (64, 2), 64 threads = 8 batch elems x 8 units. One float4 gate load/step,
// depth-4 prefetch ring.
__global__ void __launch_bounds__(64) lstm_bi_kernel(
    const float* __restrict__ Whhf, const float* __restrict__ Whhb)
{
    __shared__ float Whh[32][9];
    const int tid = threadIdx.x;
    const int dir = blockIdx.y;
    {
        const float* W = dir ? Whhb : Whhf;
        for (int i = tid; i < 256; i += 64) Whh[i >> 3][i & 7] = W[i];
    }
    __syncthreads();

    const int e = tid >> 3, u = tid & 7;
    const int b = blockIdx.x * 8 + e;
    const int base = tid & 24;   // lane-group base within warp

    float hv[8];
    #pragma unroll
    for (int j = 0; j < 8; j++) hv[j] = 0.f;
    float cu = 0.f;

    const float4* xsrc = (const float4*)g_xproj;
    const long long stride4 = (long long)B_ * 16;
    const int tt0 = dir ? (T_ - 1) : 0;
    const long long step = dir ? -stride4 : stride4;
    long long idx = ((long long)tt0 * B_ + b) * 16 + dir * 8 + u;

    float4 buf[4];
    #pragma unroll
    for (int p = 0; p < 4; p++) buf[p] = xsrc[idx + p * step];

    float* hp0 = g_h + (size_t)b * 16 + dir * 8 + u;

    #pragma unroll 4
    for (int s = 0; s < T_; s++) {
        const int tt = dir ? (T_ - 1 - s) : s;
        float4 x = buf[s & 3];
        if (s + 4 < T_) buf[s & 3] = xsrc[idx + (long long)(s + 4) * step];

        float gi = x.x, gf = x.y, gg = x.z, go = x.w;
        #pragma unroll
        for (int j = 0; j < 8; j++) {
            float h = hv[j];
            gi = __fmaf_rn(Whh[u][j],      h, gi);
            gf = __fmaf_rn(Whh[8 + u][j],  h, gf);
            gg = __fmaf_rn(Whh[16 + u][j], h, gg);
            go = __fmaf_rn(Whh[24 + u][j], h, go);
        }
        float ii = sigm(gi), ff = sigm(gf), g2 = tanh_f(gg), oo = sigm(go);
        cu = __fmaf_rn(ff, cu, ii * g2);
        float hu = oo * tanh_f(cu);
        hp0[(size_t)tt * (B_ * 16)] = hu;
        #pragma unroll
        for (int j = 0; j < 8; j++)
            hv[j] = __shfl_sync(0xffffffffu, hu, base + j);
    }
}

// ---------------- K3: ptr-LSTM input projection  zproj = h @ Wih_p^T + bias -------
// Weight rows permuted at load: output lands gate-interleaved [u][4].
__global__ void __launch_bounds__(256) zproj_kernel(
    const float* __restrict__ Wihp, const float* __restrict__ bip,
    const float* __restrict__ bhp)
{
    __shared__ float W[64][16];
    __shared__ float bias[64];
    const int tid = threadIdx.x;
    #pragma unroll
    for (int i = tid; i < 1024; i += 256) {
        int n = i >> 4, k = i & 15;
        int u = n >> 2, g = n & 3;
        W[n][k] = Wihp[(g * 16 + u) * 16 + k];     // permuted row
    }
    if (tid < 64) {
        int u = tid >> 2, g = tid & 3;
        int r = g * 16 + u;
        bias[tid] = bip[r] + bhp[r];
    }
    __syncthreads();

    size_t r = (size_t)blockIdx.x * 256 + tid;
    const float4* h4 = (const float4*)(g_h + r * 16);
    float4 a0 = h4[0], a1 = h4[1], a2 = h4[2], a3 = h4[3];
    float hr[16] = {a0.x, a0.y, a0.z, a0.w, a1.x, a1.y, a1.z, a1.w,
                    a2.x, a2.y, a2.z, a2.w, a3.x, a3.y, a3.z, a3.w};
    float* out = g_zproj + r * 64;
    #pragma unroll
    for (int g0 = 0; g0 < 64; g0 += 4) {
        float o[4];
        #pragma unroll
        for (int q = 0; q < 4; q++) {
            int g = g0 + q;
            float a = bias[g];
            #pragma unroll
            for (int k = 0; k < 16; k++) a = __fmaf_rn(W[g][k], hr[k], a);
            o[q] = a;
        }
        *(float4*)(out + g0) = make_float4(o[0], o[1], o[2], o[3]);
    }
}

// ---------------- K4: ptr LSTM scan (H=16) ----------------
// grid 128, 64 threads = 4 elems x 16 units. One float4 gate load/step, prefetch ring,
// split 8+8 recurrent accumulators per gate.
__global__ void __launch_bounds__(64) lstm_ptr_kernel(const float* __restrict__ Whhp)
{
    __shared__ float Whh[64][17];
    const int tid = threadIdx.x;
    for (int i = tid; i < 1024; i += 64) Whh[i >> 4][i & 15] = Whhp[i];
    __syncthreads();

    const int e = tid >> 4, u = tid & 15;
    const int b = blockIdx.x * 4 + e;
    const int base = tid & 16;

    float hv[16];
    #pragma unroll
    for (int j = 0; j < 16; j++) hv[j] = 0.f;
    float cu = 0.f;

    const float4* zsrc = (const float4*)g_zproj;
    const long long stride4 = (long long)B_ * 16;
    long long idx = (long long)b * 16 + u;

    float4 buf[4];
    #pragma unroll
    for (int p = 0; p < 4; p++) buf[p] = zsrc[idx + p * stride4];

    float* zp0 = g_z + (size_t)b * 16 + u;

    #pragma unroll 4
    for (int t = 0; t < T_; t++) {
        float4 x = buf[t & 3];
        if (t + 4 < T_) buf[t & 3] = zsrc[idx + (long long)(t + 4) * stride4];

        float gi0 = x.x, gf0 = x.y, gg0 = x.z, go0 = x.w;
        float gi1 = 0.f, gf1 = 0.f, gg1 = 0.f, go1 = 0.f;
        #pragma unroll
        for (int j = 0; j < 8; j++) {
            float h0 = hv[j], h1 = hv[j + 8];
            gi0 = __fmaf_rn(Whh[u][j],          h0, gi0);
            gi1 = __fmaf_rn(Whh[u][j + 8],      h1, gi1);
            gf0 = __fmaf_rn(Whh[16 + u][j],     h0, gf0);
            gf1 = __fmaf_rn(Whh[16 + u][j + 8], h1, gf1);
            gg0 = __fmaf_rn(Whh[32 + u][j],     h0, gg0);
            gg1 = __fmaf_rn(Whh[32 + u][j + 8], h1, gg1);
            go0 = __fmaf_rn(Whh[48 + u][j],     h0, go0);
            go1 = __fmaf_rn(Whh[48 + u][j + 8], h1, go1);
        }
        float ii = sigm(gi0 + gi1), ff = sigm(gf0 + gf1);
        float g2 = tanh_f(gg0 + gg1), oo = sigm(go0 + go1);
        cu = __fmaf_rn(ff, cu, ii * g2);
        float hu = oo * tanh_f(cu);
        zp0[(size_t)t * (B_ * 16)] = hu;
        #pragma unroll
        for (int j = 0; j < 16; j++)
            hv[j] = __shfl_sync(0xffffffffu, hu, base + j);
    }
}

// ---------------- K5: fused attention + output head, one CTA per t ----------------
#define ATT_SMEM_FLOATS (8192 + 8192 + 512 + 256 + 256 + 16)
__global__ void __launch_bounds__(512) attn_kernel(
    const float* __restrict__ W_h, const float* __restrict__ W_e,
    const float* __restrict__ W_v, float* __restrict__ out)
{
    extern __shared__ __align__(16) float sm[];
    float* hs   = sm;            // 512 x 16
    float* zs   = sm + 8192;     // 512 x 16
    float* cinv = sm + 16384;    // 512
    float* whs  = sm + 16896;    // 16 x 16
    float* wes  = sm + 17152;    // 16 x 16
    float* wvs  = sm + 17408;    // 16

    const int tid = threadIdx.x;
    const int t = blockIdx.x;
    {
        const float4* hsrc = (const float4*)(g_h + (size_t)t * (B_ * 16));
        const float4* zsrc = (const float4*)(g_z + (size_t)t * (B_ * 16));
        float4* hd = (float4*)hs;
        float4* zd = (float4*)zs;
        #pragma unroll
        for (int i = 0; i < 4; i++) {
            hd[tid + i * 512] = hsrc[tid + i * 512];
            zd[tid + i * 512] = zsrc[tid + i * 512];
        }
    }
    if (tid < 256) { whs[tid] = W_h[tid]; wes[tid] = W_e[tid]; }
    if (tid < 16)  wvs[tid] = W_v[tid];
    __syncthreads();

    // ---- pass 1: thread c owns column c -> colsum ----
    {
        const ulonglong2* zr = (const ulonglong2*)(zs + tid * 16);
        ulonglong2 zq0 = zr[0], zq1 = zr[1], zq2 = zr[2], zq3 = zr[3];
        float colsum = 0.f;
        #pragma unroll 2
        for (int bb = 0; bb < B_; bb++) {
            const ulonglong2* hr = (const ulonglong2*)(hs + bb * 16);
            ulonglong2 hq0 = hr[0], hq1 = hr[1], hq2 = hr[2], hq3 = hr[3];
            ull aA = 0ULL, aB = 0ULL;
            aA = ffma2(hq0.x, zq0.x, aA); aB = ffma2(hq0.y, zq0.y, aB);
            aA = ffma2(hq1.x, zq1.x, aA); aB = ffma2(hq1.y, zq1.y, aB);
            aA = ffma2(hq2.x, zq2.x, aA); aB = ffma2(hq2.y, zq2.y, aB);
            aA = ffma2(hq3.x, zq3.x, aA); aB = ffma2(hq3.y, zq3.y, aB);
            float2 va = unpack2(aA), vb = unpack2(aB);
            float S = (va.x + va.y) + (vb.x + vb.y);
            colsum += __expf(S);
        }
        cinv[tid] = __fdividef(1.f, colsum);
    }
    __syncthreads();

    // ---- pass 2 + output head: thread b owns row b ----
    {
        const ulonglong2* hrp = (const ulonglong2*)(hs + tid * 16);
        ulonglong2 hq0 = hrp[0], hq1 = hrp[1], hq2 = hrp[2], hq3 = hrp[3];
        ull cacc[8];
        #pragma unroll
        for (int k = 0; k < 8; k++) cacc[k] = 0ULL;

        #pragma unroll 2
        for (int c = 0; c < B_; c++) {
            const ulonglong2* zr = (const ulonglong2*)(zs + c * 16);
            ulonglong2 zq0 = zr[0], zq1 = zr[1], zq2 = zr[2], zq3 = zr[3];
            ull aA = 0ULL, aB = 0ULL;
            aA = ffma2(hq0.x, zq0.x, aA); aB = ffma2(hq0.y, zq0.y, aB);
            aA = ffma2(hq1.x, zq1.x, aA); aB = ffma2(hq1.y, zq1.y, aB);
            aA = ffma2(hq2.x, zq2.x, aA); aB = ffma2(hq2.y, zq2.y, aB);
            aA = ffma2(hq3.x, zq3.x, aA); aB = ffma2(hq3.y, zq3.y, aB);
            float2 va = unpack2(aA), vb = unpack2(aB);
            float S = (va.x + va.y) + (vb.x + vb.y);
            float w = __expf(S) * cinv[c];
            ull w2 = pack2(w, w);
            const ulonglong2* hc = (const ulonglong2*)(hs + c * 16);
            ulonglong2 hcq0 = hc[0], hcq1 = hc[1], hcq2 = hc[2], hcq3 = hc[3];
            cacc[0] = ffma2(hcq0.x, w2, cacc[0]); cacc[1] = ffma2(hcq0.y, w2, cacc[1]);
            cacc[2] = ffma2(hcq1.x, w2, cacc[2]); cacc[3] = ffma2(hcq1.y, w2, cacc[3]);
            cacc[4] = ffma2(hcq2.x, w2, cacc[4]); cacc[5] = ffma2(hcq2.y, w2, cacc[5]);
            cacc[6] = ffma2(hcq3.x, w2, cacc[6]); cacc[7] = ffma2(hcq3.y, w2, cacc[7]);
        }

        float ctxv[16], hbv[16];
        #pragma unroll
        for (int k = 0; k < 8; k++) {
            float2 v = unpack2(cacc[k]);
            ctxv[2 * k] = v.x; ctxv[2 * k + 1] = v.y;
        }
        {
            float2 v;
            v = unpack2(hq0.x); hbv[0] = v.x;  hbv[1] = v.y;
            v = unpack2(hq0.y); hbv[2] = v.x;  hbv[3] = v.y;
            v = unpack2(hq1.x); hbv[4] = v.x;  hbv[5] = v.y;
            v = unpack2(hq1.y); hbv[6] = v.x;  hbv[7] = v.y;
            v = unpack2(hq2.x); hbv[8] = v.x;  hbv[9] = v.y;
            v = unpack2(hq2.y); hbv[10] = v.x; hbv[11] = v.y;
            v = unpack2(hq3.x); hbv[12] = v.x; hbv[13] = v.y;
            v = unpack2(hq3.y); hbv[14] = v.x; hbv[15] = v.y;
        }
        float pacc = 0.f;
        #pragma unroll
        for (int d = 0; d < 16; d++) {
            float a = 0.f;
            #pragma unroll
            for (int k = 0; k < 16; k++) a = __fmaf_rn(whs[d * 16 + k], hbv[k], a);
            #pragma unroll
            for (int k = 0; k < 16; k++) a = __fmaf_rn(wes[d * 16 + k], ctxv[k], a);
            float ud = tanh_f(a);
            pacc = __fmaf_rn(ud, wvs[d], pacc);
        }
        out[(size_t)t * B_ + tid] = sigm(pacc);
    }
}

// ---------------- launch ----------------
extern "C" void kernel_launch(void* const* d_in, const int* in_sizes, int n_in,
                              void* d_out, int out_size)
{
    (void)in_sizes; (void)n_in; (void)out_size;
    const float* X     = (const float*)d_in[0];
    const float* Wih_f = (const float*)d_in[1];
    const float* Whh_f = (const float*)d_in[2];
    const float* bih_f = (const float*)d_in[3];
    const float* bhh_f = (const float*)d_in[4];
    const float* Wih_b = (const float*)d_in[5];
    const float* Whh_b = (const float*)d_in[6];
    const float* bih_b = (const float*)d_in[7];
    const float* bhh_b = (const float*)d_in[8];
    const float* Wih_p = (const float*)d_in[9];
    const float* Whh_p = (const float*)d_in[10];
    const float* bih_p = (const float*)d_in[11];
    const float* bhh_p = (const float*)d_in[12];
    const float* W_h   = (const float*)d_in[13];
    const float* W_e   = (const float*)d_in[14];
    const float* W_v   = (const float*)d_in[15];
    float* out = (float*)d_out;

    proj_kernel<<<256, 256>>>(X, Wih_f, Wih_b, bih_f, bhh_f, bih_b, bhh_b);
    lstm_bi_kernel<<<dim3(64, 2), 64>>>(Whh_f, Whh_b);
    zproj_kernel<<<256, 256>>>(Wih_p, bih_p, bhh_p);
    lstm_ptr_kernel<<<128, 64>>>(Whh_p);

    const int att_smem = ATT_SMEM_FLOATS * (int)sizeof(float);  // ~69.7 KB
    cudaFuncSetAttribute(attn_kernel, cudaFuncAttributeMaxDynamicSharedMemorySize, att_smem);
    attn_kernel<<<128, 512, att_smem>>>(W_h, W_e, W_v, out);
}

// round 6
// speedup vs baseline: 1.4656x; 1.3948x over previous
#include <cuda_runtime.h>
#include <cuda_bf16.h>
#include <cstdint>

#define T_ 128
#define B_ 512
#define D_ 768
#define R_ (T_*B_)   // 65536 rows

typedef unsigned long long ull;

// ---------------- scratch (static device globals; no allocation) ----------------
__device__ __align__(16) float g_xproj[R_ * 64];  // [t][b][dir][u][4] : col = dir*32 + u*4 + gate
__device__ __align__(16) float g_h[R_ * 16];      // [t][b][16]: 0..7 fwd h, 8..15 bwd h
__device__ __align__(16) float g_zproj[R_ * 64];  // [t][b][u][4]
__device__ __align__(16) float g_z[R_ * 16];      // ptr-LSTM hidden states

// ---------------- helpers ----------------
__device__ __forceinline__ ull ffma2(ull a, ull b, ull c) {
    ull d;
    asm("fma.rn.f32x2 %0, %1, %2, %3;" : "=l"(d) : "l"(a), "l"(b), "l"(c));
    return d;
}
__device__ __forceinline__ ull add2(ull a, ull b) {
    ull d;
    asm("add.rn.f32x2 %0, %1, %2;" : "=l"(d) : "l"(a), "l"(b));
    return d;
}
__device__ __forceinline__ ull pack2(float lo, float hi) {
    ull r;
    asm("mov.b64 %0, {%1, %2};" : "=l"(r) : "f"(lo), "f"(hi));
    return r;
}
__device__ __forceinline__ float2 unpack2(ull v) {
    float lo, hi;
    asm("mov.b64 {%0, %1}, %2;" : "=f"(lo), "=f"(hi) : "l"(v));
    return make_float2(lo, hi);
}
__device__ __forceinline__ float sigm(float x) {
    return __fdividef(1.f, 1.f + __expf(-x));
}
__device__ __forceinline__ float tanh_f(float x) {
    return __fmaf_rn(2.f, sigm(2.f * x), -1.f);
}
__device__ __forceinline__ uint32_t smem_u32(const void* p) {
    uint32_t a;
    asm("{ .reg .u64 t; cvta.to.shared.u64 t, %1; cvt.u32.u64 %0, t; }" : "=r"(a) : "l"(p));
    return a;
}

// map output column c (0..63) of the big projection to the original W row.
// layout: dir = c>>5, u = (c&31)>>2, gate = (c&31)&3 ; orig row = gate*8 + u
__device__ __forceinline__ int bi_row_of_col(int c, int& dir) {
    dir = c >> 5;
    int w = c & 31;
    return (w & 3) * 8 + (w >> 2);
}

// ---------------- warp MMA (HMMA, plain PTX — works on bare sm_103) ----------------
__device__ __forceinline__ void mma_bf16(float* c, const uint32_t* a, uint32_t b0, uint32_t b1) {
    asm volatile(
        "mma.sync.aligned.m16n8k16.row.col.f32.bf16.bf16.f32 "
        "{%0,%1,%2,%3}, {%4,%5,%6,%7}, {%8,%9}, {%0,%1,%2,%3};"
        : "+f"(c[0]), "+f"(c[1]), "+f"(c[2]), "+f"(c[3])
        : "r"(a[0]), "r"(a[1]), "r"(a[2]), "r"(a[3]), "r"(b0), "r"(b1));
}
__device__ __forceinline__ void ldm4(uint32_t* r, uint32_t addr) {
    asm volatile("ldmatrix.sync.aligned.m8n8.x4.shared.b16 {%0,%1,%2,%3}, [%4];"
                 : "=r"(r[0]), "=r"(r[1]), "=r"(r[2]), "=r"(r[3]) : "r"(addr));
}

// ---------------- K1: HMMA projection GEMM ----------------
// C[R x 64] = X[R x 768] @ Wperm^T + bias, bf16 hi/lo split (3 MMAs), fp32 accum.
// Per CTA: M=128 rows, N=64, K in 12 chunks of 64. 256 threads = 8 warps; warp w
// owns rows 16w..16w+15, all 64 cols (8 n-tiles of 8).
#define PA_HI 0
#define PA_LO 16384
#define PB_HI 32768
#define PB_LO 40960
#define PROJ_SMEM 49152
#define NKC 12

__device__ __forceinline__ void cvt_hilo8(float4 v0, float4 v1, uint4& hi, uint4& lo) {
    float xs[8] = {v0.x, v0.y, v0.z, v0.w, v1.x, v1.y, v1.z, v1.w};
    uint32_t h[4], l[4];
    #pragma unroll
    for (int i = 0; i < 4; i++) {
        float a = xs[2 * i], b = xs[2 * i + 1];
        uint32_t hp;
        asm("cvt.rn.bf16x2.f32 %0, %1, %2;" : "=r"(hp) : "f"(b), "f"(a)); // lo16=a, hi16=b
        float fa = __uint_as_float(hp << 16);
        float fb = __uint_as_float(hp & 0xffff0000u);
        float la = a - fa, lb = b - fb;
        uint32_t lp;
        asm("cvt.rn.bf16x2.f32 %0, %1, %2;" : "=r"(lp) : "f"(lb), "f"(la));
        h[i] = hp; l[i] = lp;
    }
    hi = make_uint4(h[0], h[1], h[2], h[3]);
    lo = make_uint4(l[0], l[1], l[2], l[3]);
}

__global__ void __launch_bounds__(256) proj_mma_kernel(
    const float* __restrict__ X,
    const float* __restrict__ Wf, const float* __restrict__ Wb,
    const float* __restrict__ bif, const float* __restrict__ bhf,
    const float* __restrict__ bib, const float* __restrict__ bhb)
{
    extern __shared__ __align__(1024) char psm[];
    __shared__ float bias[64];
    const uint32_t smem_base = smem_u32(psm);
    const int tid = threadIdx.x;
    const int w = tid >> 5, lane = tid & 31;
    const int row0 = blockIdx.x * 128;

    if (tid < 64) {
        int dir;
        int r = bi_row_of_col(tid, dir);
        bias[tid] = dir ? (bib[r] + bhb[r]) : (bif[r] + bhf[r]);
    }

    // ldmatrix address precompute (swizzle: koffbits ^= (row&7)<<4 within 128B rows)
    const int rowA = 16 * w + (lane & 15);
    const uint32_t aRow = smem_base + rowA * 128;
    const uint32_t axr = (rowA & 7) << 4;
    const uint32_t akoff = (lane >= 16) ? 16u : 0u;

    const int nB = (lane & 7) + ((lane >> 4) << 3);   // 0..15 within a 16-row n-pair block
    const uint32_t bxr = (lane & 7) << 4;
    const uint32_t bkoff = (lane & 8) ? 16u : 0u;

    float acc[32];
    #pragma unroll
    for (int i = 0; i < 32; i++) acc[i] = 0.f;

    for (int kc = 0; kc < NKC; kc++) {
        const int k0 = kc * 64;
        // stage gmem loads into registers (overlaps with previous chunk's MMAs)
        float4 areg[8], breg[4];
        #pragma unroll
        for (int q = 0; q < 4; q++) {
            int unit = tid + q * 256;
            int r = unit >> 3, c8 = unit & 7;
            const float* p = X + (size_t)(row0 + r) * D_ + k0 + c8 * 8;
            areg[2 * q]     = *(const float4*)p;
            areg[2 * q + 1] = *(const float4*)(p + 4);
        }
        #pragma unroll
        for (int q = 0; q < 2; q++) {
            int unit = tid + q * 256;
            int n = unit >> 3, c8 = unit & 7;
            int dir;
            int rr = bi_row_of_col(n, dir);
            const float* p = (dir ? Wb : Wf) + rr * D_ + k0 + c8 * 8;
            breg[2 * q]     = *(const float4*)p;
            breg[2 * q + 1] = *(const float4*)(p + 4);
        }
        __syncthreads();   // previous chunk's ldmatrix reads done before overwrite

        // convert + swizzled store (bf16 hi/lo tiles, 128B rows)
        #pragma unroll
        for (int q = 0; q < 4; q++) {
            int unit = tid + q * 256;
            int r = unit >> 3, c8 = unit & 7;
            uint32_t off = r * 128 + c8 * 16;
            uint32_t sw = off ^ ((off >> 3) & 0x70);
            uint4 hi, lo;
            cvt_hilo8(areg[2 * q], areg[2 * q + 1], hi, lo);
            *(uint4*)(psm + PA_HI + sw) = hi;
            *(uint4*)(psm + PA_LO + sw) = lo;
        }
        #pragma unroll
        for (int q = 0; q < 2; q++) {
            int unit = tid + q * 256;
            int n = unit >> 3, c8 = unit & 7;
            uint32_t off = n * 128 + c8 * 16;
            uint32_t sw = off ^ ((off >> 3) & 0x70);
            uint4 hi, lo;
            cvt_hilo8(breg[2 * q], breg[2 * q + 1], hi, lo);
            *(uint4*)(psm + PB_HI + sw) = hi;
            *(uint4*)(psm + PB_LO + sw) = lo;
        }
        __syncthreads();

        // 4 k-steps of m16n8k16 over 8 n-tiles, hi/lo 3-product split
        #pragma unroll
        for (int ks = 0; ks < 4; ks++) {
            const uint32_t ak = (ks * 32 + akoff) ^ axr;
            uint32_t ahi[4], alo[4];
            ldm4(ahi, aRow + PA_HI + ak);
            ldm4(alo, aRow + PA_LO + ak);
            #pragma unroll
            for (int np = 0; np < 4; np++) {
                const int n = np * 16 + nB;
                const uint32_t bk = (uint32_t)n * 128 + ((ks * 32 + bkoff) ^ bxr);
                uint32_t bhi[4], blo[4];
                ldm4(bhi, smem_base + PB_HI + bk);
                ldm4(blo, smem_base + PB_LO + bk);
                float* c0 = acc + (2 * np) * 4;
                float* c1 = acc + (2 * np + 1) * 4;
                mma_bf16(c0, ahi, bhi[0], bhi[1]);
                mma_bf16(c0, ahi, blo[0], blo[1]);
                mma_bf16(c0, alo, bhi[0], bhi[1]);
                mma_bf16(c1, ahi, bhi[2], bhi[3]);
                mma_bf16(c1, ahi, blo[2], blo[3]);
                mma_bf16(c1, alo, bhi[2], bhi[3]);
            }
        }
    }

    // epilogue: C fragment rows 16w+g / 16w+8+g, cols nt*8 + 2*(lane&3) + {0,1}
    const int g = lane >> 2, tq = (lane & 3) * 2;
    const int r0 = row0 + 16 * w + g;
    #pragma unroll
    for (int nt = 0; nt < 8; nt++) {
        int col = nt * 8 + tq;
        float b0 = bias[col], b1 = bias[col + 1];
        float* d0 = g_xproj + (size_t)r0 * 64 + col;
        float* d1 = g_xproj + (size_t)(r0 + 8) * 64 + col;
        *(float2*)d0 = make_float2(acc[nt * 4 + 0] + b0, acc[nt * 4 + 1] + b1);
        *(float2*)d1 = make_float2(acc[nt * 4 + 2] + b0, acc[nt * 4 + 3] + b1);
    }
}

// ---------------- scan dot helpers ----------------
__device__ __forceinline__ float dot8(ulonglong2 hA, ulonglong2 hB,
                                      ulonglong2 w01, ulonglong2 w23, float x) {
    ull a0 = ffma2(hB.x, w23.x, ffma2(hA.x, w01.x, 0ULL));
    ull a1 = ffma2(hB.y, w23.y, ffma2(hA.y, w01.y, 0ULL));
    float2 v = unpack2(add2(a0, a1));
    return x + v.x + v.y;
}
__device__ __forceinline__ float dot16(ulonglong2 hA, ulonglong2 hB,
                                       ulonglong2 hC, ulonglong2 hD,
                                       ulonglong2 w0, ulonglong2 w1,
                                       ulonglong2 w2, ulonglong2 w3, float x) {
    ull a0 = ffma2(hC.x, w2.x, ffma2(hA.x, w0.x, 0ULL));
    ull a1 = ffma2(hC.y, w2.y, ffma2(hA.y, w0.y, 0ULL));
    ull a2 = ffma2(hD.x, w3.x, ffma2(hB.x, w1.x, 0ULL));
    ull a3 = ffma2(hD.y, w3.y, ffma2(hB.y, w1.y, 0ULL));
    float2 v = unpack2(add2(add2(a0, a1), add2(a2, a3)));
    return x + v.x + v.y;
}

// ---------------- K2: bidirectional LSTM scan (H=8) ----------------
// grid (64, 2), 64 threads = 8 elems x 8 units. Weights in registers,
// h-exchange via double-buffered smem, one float4 gate load/step.
__global__ void __launch_bounds__(64) lstm_bi_kernel(
    const float* __restrict__ Whhf, const float* __restrict__ Whhb)
{
    __shared__ __align__(32) float hsm[2][8][8];
    const int tid = threadIdx.x;
    const int dir = blockIdx.y;
    const int e = tid >> 3, u = tid & 7;
    const int b = blockIdx.x * 8 + e;

    const float* W = dir ? Whhb : Whhf;
    ulonglong2 wi0 = *(const ulonglong2*)(W + u * 8);
    ulonglong2 wi1 = *(const ulonglong2*)(W + u * 8 + 4);
    ulonglong2 wf0 = *(const ulonglong2*)(W + (8 + u) * 8);
    ulonglong2 wf1 = *(const ulonglong2*)(W + (8 + u) * 8 + 4);
    ulonglong2 wg0 = *(const ulonglong2*)(W + (16 + u) * 8);
    ulonglong2 wg1 = *(const ulonglong2*)(W + (16 + u) * 8 + 4);
    ulonglong2 wo0 = *(const ulonglong2*)(W + (24 + u) * 8);
    ulonglong2 wo1 = *(const ulonglong2*)(W + (24 + u) * 8 + 4);

    hsm[0][e][u] = 0.f;
    __syncthreads();
    float cu = 0.f;

    const float4* xsrc = (const float4*)g_xproj;
    const long long stride4 = (long long)B_ * 16;
    const long long step = dir ? -stride4 : stride4;
    long long idx = ((long long)(dir ? T_ - 1 : 0) * B_ + b) * 16 + dir * 8 + u;
    float4 buf[4];
    #pragma unroll
    for (int p = 0; p < 4; p++) buf[p] = xsrc[idx + p * step];

    float* hp0 = g_h + (size_t)b * 16 + dir * 8 + u;

    for (int s = 0; s < T_; s++) {
        const int tt = dir ? (T_ - 1 - s) : s;
        float4 x = buf[s & 3];
        if (s + 4 < T_) buf[s & 3] = xsrc[idx + (long long)(s + 4) * step];
        const int p = s & 1;
        ulonglong2 hA = *(const ulonglong2*)&hsm[p][e][0];
        ulonglong2 hB = *(const ulonglong2*)&hsm[p][e][4];

        float gi = dot8(hA, hB, wi0, wi1, x.x);
        float gf = dot8(hA, hB, wf0, wf1, x.y);
        float gg = dot8(hA, hB, wg0, wg1, x.z);
        float go = dot8(hA, hB, wo0, wo1, x.w);

        float ii = sigm(gi), ff = sigm(gf), g2 = tanh_f(gg), oo = sigm(go);
        cu = __fmaf_rn(ff, cu, ii * g2);
        float hu = oo * tanh_f(cu);
        hsm[p ^ 1][e][u] = hu;
        __syncwarp();
        hp0[(size_t)tt * (B_ * 16)] = hu;
    }
}

// ---------------- K3: ptr-LSTM input projection (gate-interleaved output) -------
__global__ void __launch_bounds__(256) zproj_kernel(
    const float* __restrict__ Wihp, const float* __restrict__ bip,
    const float* __restrict__ bhp)
{
    __shared__ float W[64][16];
    __shared__ float bias[64];
    const int tid = threadIdx.x;
    #pragma unroll
    for (int i = tid; i < 1024; i += 256) {
        int n = i >> 4, k = i & 15;
        int u = n >> 2, g = n & 3;
        W[n][k] = Wihp[(g * 16 + u) * 16 + k];
    }
    if (tid < 64) {
        int u = tid >> 2, g = tid & 3;
        int r = g * 16 + u;
        bias[tid] = bip[r] + bhp[r];
    }
    __syncthreads();

    size_t r = (size_t)blockIdx.x * 256 + tid;
    const float4* h4 = (const float4*)(g_h + r * 16);
    float4 a0 = h4[0], a1 = h4[1], a2 = h4[2], a3 = h4[3];
    float hr[16] = {a0.x, a0.y, a0.z, a0.w, a1.x, a1.y, a1.z, a1.w,
                    a2.x, a2.y, a2.z, a2.w, a3.x, a3.y, a3.z, a3.w};
    float* out = g_zproj + r * 64;
    #pragma unroll
    for (int g0 = 0; g0 < 64; g0 += 4) {
        float o[4];
        #pragma unroll
        for (int q = 0; q < 4; q++) {
            int g = g0 + q;
            float a = bias[g];
            #pragma unroll
            for (int k = 0; k < 16; k++) a = __fmaf_rn(W[g][k], hr[k], a);
            o[q] = a;
        }
        *(float4*)(out + g0) = make_float4(o[0], o[1], o[2], o[3]);
    }
}

// ---------------- K4: ptr LSTM scan (H=16) ----------------
// grid 128, 64 threads = 4 elems x 16 units. Weights in registers,
// smem h-exchange, f32x2 dot chains.
__global__ void __launch_bounds__(64) lstm_ptr_kernel(const float* __restrict__ Whhp)
{
    __shared__ __align__(64) float hsm[2][4][16];
    const int tid = threadIdx.x;
    const int e = tid >> 4, u = tid & 15;
    const int b = blockIdx.x * 4 + e;

    ulonglong2 wi[4], wf4[4], wg4[4], wo4[4];
    {
        const ulonglong2* p;
        p = (const ulonglong2*)(Whhp + u * 16);
        wi[0] = p[0]; wi[1] = p[1]; wi[2] = p[2]; wi[3] = p[3];
        p = (const ulonglong2*)(Whhp + (16 + u) * 16);
        wf4[0] = p[0]; wf4[1] = p[1]; wf4[2] = p[2]; wf4[3] = p[3];
        p = (const ulonglong2*)(Whhp + (32 + u) * 16);
        wg4[0] = p[0]; wg4[1] = p[1]; wg4[2] = p[2]; wg4[3] = p[3];
        p = (const ulonglong2*)(Whhp + (48 + u) * 16);
        wo4[0] = p[0]; wo4[1] = p[1]; wo4[2] = p[2]; wo4[3] = p[3];
    }

    hsm[0][e][u] = 0.f;
    __syncthreads();
    float cu = 0.f;

    const float4* zsrc = (const float4*)g_zproj;
    const long long stride4 = (long long)B_ * 16;
    long long idx = (long long)b * 16 + u;
    float4 buf[4];
    #pragma unroll
    for (int p = 0; p < 4; p++) buf[p] = zsrc[idx + p * stride4];

    float* zp0 = g_z + (size_t)b * 16 + u;

    for (int t = 0; t < T_; t++) {
        float4 x = buf[t & 3];
        if (t + 4 < T_) buf[t & 3] = zsrc[idx + (long long)(t + 4) * stride4];
        const int p = t & 1;
        const ulonglong2* hr = (const ulonglong2*)&hsm[p][e][0];
        ulonglong2 hA = hr[0], hB = hr[1], hC = hr[2], hD = hr[3];

        float gi = dot16(hA, hB, hC, hD, wi[0], wi[1], wi[2], wi[3], x.x);
        float gf = dot16(hA, hB, hC, hD, wf4[0], wf4[1], wf4[2], wf4[3], x.y);
        float gg = dot16(hA, hB, hC, hD, wg4[0], wg4[1], wg4[2], wg4[3], x.z);
        float go = dot16(hA, hB, hC, hD, wo4[0], wo4[1], wo4[2], wo4[3], x.w);

        float ii = sigm(gi), ff = sigm(gf), g2 = tanh_f(gg), oo = sigm(go);
        cu = __fmaf_rn(ff, cu, ii * g2);
        float hu = oo * tanh_f(cu);
        hsm[p ^ 1][e][u] = hu;
        __syncwarp();
        zp0[(size_t)t * (B_ * 16)] = hu;
    }
}

// ---------------- K5: fused attention + output head, one CTA per t ----------------
#define ATT_SMEM_FLOATS (8192 + 8192 + 512 + 256 + 256 + 16)
__global__ void __launch_bounds__(512) attn_kernel(
    const float* __restrict__ W_h, const float* __restrict__ W_e,
    const float* __restrict__ W_v, float* __restrict__ out)
{
    extern __shared__ __align__(16) float sm[];
    float* hs   = sm;            // 512 x 16
    float* zs   = sm + 8192;     // 512 x 16
    float* cinv = sm + 16384;    // 512
    float* whs  = sm + 16896;    // 16 x 16
    float* wes  = sm + 17152;    // 16 x 16
    float* wvs  = sm + 17408;    // 16

    const int tid = threadIdx.x;
    const int t = blockIdx.x;
    {
        const float4* hsrc = (const float4*)(g_h + (size_t)t * (B_ * 16));
        const float4* zsrc = (const float4*)(g_z + (size_t)t * (B_ * 16));
        float4* hd = (float4*)hs;
        float4* zd = (float4*)zs;
        #pragma unroll
        for (int i = 0; i < 4; i++) {
            hd[tid + i * 512] = hsrc[tid + i * 512];
            zd[tid + i * 512] = zsrc[tid + i * 512];
        }
    }
    if (tid < 256) { whs[tid] = W_h[tid]; wes[tid] = W_e[tid]; }
    if (tid < 16)  wvs[tid] = W_v[tid];
    __syncthreads();

    // ---- pass 1: thread c owns column c -> colsum ----
    {
        const ulonglong2* zr = (const ulonglong2*)(zs + tid * 16);
        ulonglong2 zq0 = zr[0], zq1 = zr[1], zq2 = zr[2], zq3 = zr[3];
        float colsum = 0.f;
        #pragma unroll 2
        for (int bb = 0; bb < B_; bb++) {
            const ulonglong2* hr = (const ulonglong2*)(hs + bb * 16);
            ulonglong2 hq0 = hr[0], hq1 = hr[1], hq2 = hr[2], hq3 = hr[3];
            ull aA = 0ULL, aB = 0ULL;
            aA = ffma2(hq0.x, zq0.x, aA); aB = ffma2(hq0.y, zq0.y, aB);
            aA = ffma2(hq1.x, zq1.x, aA); aB = ffma2(hq1.y, zq1.y, aB);
            aA = ffma2(hq2.x, zq2.x, aA); aB = ffma2(hq2.y, zq2.y, aB);
            aA = ffma2(hq3.x, zq3.x, aA); aB = ffma2(hq3.y, zq3.y, aB);
            float2 va = unpack2(aA), vb = unpack2(aB);
            float S = (va.x + va.y) + (vb.x + vb.y);
            colsum += __expf(S);
        }
        cinv[tid] = __fdividef(1.f, colsum);
    }
    __syncthreads();

    // ---- pass 2 + output head: thread b owns row b ----
    {
        const ulonglong2* hrp = (const ulonglong2*)(hs + tid * 16);
        ulonglong2 hq0 = hrp[0], hq1 = hrp[1], hq2 = hrp[2], hq3 = hrp[3];
        ull cacc[8];
        #pragma unroll
        for (int k = 0; k < 8; k++) cacc[k] = 0ULL;

        #pragma unroll 2
        for (int c = 0; c < B_; c++) {
            const ulonglong2* zr = (const ulonglong2*)(zs + c * 16);
            ulonglong2 zq0 = zr[0], zq1 = zr[1], zq2 = zr[2], zq3 = zr[3];
            ull aA = 0ULL, aB = 0ULL;
            aA = ffma2(hq0.x, zq0.x, aA); aB = ffma2(hq0.y, zq0.y, aB);
            aA = ffma2(hq1.x, zq1.x, aA); aB = ffma2(hq1.y, zq1.y, aB);
            aA = ffma2(hq2.x, zq2.x, aA); aB = ffma2(hq2.y, zq2.y, aB);
            aA = ffma2(hq3.x, zq3.x, aA); aB = ffma2(hq3.y, zq3.y, aB);
            float2 va = unpack2(aA), vb = unpack2(aB);
            float S = (va.x + va.y) + (vb.x + vb.y);
            float w = __expf(S) * cinv[c];
            ull w2 = pack2(w, w);
            const ulonglong2* hc = (const ulonglong2*)(hs + c * 16);
            ulonglong2 hcq0 = hc[0], hcq1 = hc[1], hcq2 = hc[2], hcq3 = hc[3];
            cacc[0] = ffma2(hcq0.x, w2, cacc[0]); cacc[1] = ffma2(hcq0.y, w2, cacc[1]);
            cacc[2] = ffma2(hcq1.x, w2, cacc[2]); cacc[3] = ffma2(hcq1.y, w2, cacc[3]);
            cacc[4] = ffma2(hcq2.x, w2, cacc[4]); cacc[5] = ffma2(hcq2.y, w2, cacc[5]);
            cacc[6] = ffma2(hcq3.x, w2, cacc[6]); cacc[7] = ffma2(hcq3.y, w2, cacc[7]);
        }

        float ctxv[16], hbv[16];
        #pragma unroll
        for (int k = 0; k < 8; k++) {
            float2 v = unpack2(cacc[k]);
            ctxv[2 * k] = v.x; ctxv[2 * k + 1] = v.y;
        }
        {
            float2 v;
            v = unpack2(hq0.x); hbv[0] = v.x;  hbv[1] = v.y;
            v = unpack2(hq0.y); hbv[2] = v.x;  hbv[3] = v.y;
            v = unpack2(hq1.x); hbv[4] = v.x;  hbv[5] = v.y;
            v = unpack2(hq1.y); hbv[6] = v.x;  hbv[7] = v.y;
            v = unpack2(hq2.x); hbv[8] = v.x;  hbv[9] = v.y;
            v = unpack2(hq2.y); hbv[10] = v.x; hbv[11] = v.y;
            v = unpack2(hq3.x); hbv[12] = v.x; hbv[13] = v.y;
            v = unpack2(hq3.y); hbv[14] = v.x; hbv[15] = v.y;
        }
        float pacc = 0.f;
        #pragma unroll
        for (int d = 0; d < 16; d++) {
            float a = 0.f;
            #pragma unroll
            for (int k = 0; k < 16; k++) a = __fmaf_rn(whs[d * 16 + k], hbv[k], a);
            #pragma unroll
            for (int k = 0; k < 16; k++) a = __fmaf_rn(wes[d * 16 + k], ctxv[k], a);
            float ud = tanh_f(a);
            pacc = __fmaf_rn(ud, wvs[d], pacc);
        }
        out[(size_t)t * B_ + tid] = sigm(pacc);
    }
}

// ---------------- launch ----------------
extern "C" void kernel_launch(void* const* d_in, const int* in_sizes, int n_in,
                              void* d_out, int out_size)
{
    (void)in_sizes; (void)n_in; (void)out_size;
    const float* X     = (const float*)d_in[0];
    const float* Wih_f = (const float*)d_in[1];
    const float* Whh_f = (const float*)d_in[2];
    const float* bih_f = (const float*)d_in[3];
    const float* bhh_f = (const float*)d_in[4];
    const float* Wih_b = (const float*)d_in[5];
    const float* Whh_b = (const float*)d_in[6];
    const float* bih_b = (const float*)d_in[7];
    const float* bhh_b = (const float*)d_in[8];
    const float* Wih_p = (const float*)d_in[9];
    const float* Whh_p = (const float*)d_in[10];
    const float* bih_p = (const float*)d_in[11];
    const float* bhh_p = (const float*)d_in[12];
    const float* W_h   = (const float*)d_in[13];
    const float* W_e   = (const float*)d_in[14];
    const float* W_v   = (const float*)d_in[15];
    float* out = (float*)d_out;

    cudaFuncSetAttribute(proj_mma_kernel, cudaFuncAttributeMaxDynamicSharedMemorySize, PROJ_SMEM);
    proj_mma_kernel<<<R_ / 128, 256, PROJ_SMEM>>>(X, Wih_f, Wih_b, bih_f, bhh_f, bih_b, bhh_b);

    lstm_bi_kernel<<<dim3(64, 2), 64>>>(Whh_f, Whh_b);
    zproj_kernel<<<256, 256>>>(Wih_p, bih_p, bhh_p);
    lstm_ptr_kernel<<<128, 64>>>(Whh_p);

    const int att_smem = ATT_SMEM_FLOATS * (int)sizeof(float);  // ~69.7 KB
    cudaFuncSetAttribute(attn_kernel, cudaFuncAttributeMaxDynamicSharedMemorySize, att_smem);
    attn_kernel<<<128, 512, att_smem>>>(W_h, W_e, W_v, out);
}

// round 7
// speedup vs baseline: 1.6862x; 1.1505x over previous
#include <cuda_runtime.h>
#include <cuda_bf16.h>
#include <cstdint>

#define T_ 128
#define B_ 512
#define D_ 768
#define R_ (T_*B_)   // 65536 rows

typedef unsigned long long ull;

// ---------------- scratch (static device globals; no allocation) ----------------
__device__ __align__(16) float g_xproj[R_ * 64];  // [t][b][dir][u][4] : col = dir*32 + u*4 + gate
__device__ __align__(16) float g_h[R_ * 16];      // [t][b][16]: 0..7 fwd h, 8..15 bwd h
__device__ __align__(16) float g_zproj[R_ * 64];  // [t][b][u][4]
__device__ __align__(16) float g_z[R_ * 16];      // ptr-LSTM hidden states

// ---------------- helpers ----------------
__device__ __forceinline__ ull ffma2(ull a, ull b, ull c) {
    ull d;
    asm("fma.rn.f32x2 %0, %1, %2, %3;" : "=l"(d) : "l"(a), "l"(b), "l"(c));
    return d;
}
__device__ __forceinline__ ull add2(ull a, ull b) {
    ull d;
    asm("add.rn.f32x2 %0, %1, %2;" : "=l"(d) : "l"(a), "l"(b));
    return d;
}
__device__ __forceinline__ ull pack2(float lo, float hi) {
    ull r;
    asm("mov.b64 %0, {%1, %2};" : "=l"(r) : "f"(lo), "f"(hi));
    return r;
}
__device__ __forceinline__ float2 unpack2(ull v) {
    float lo, hi;
    asm("mov.b64 {%0, %1}, %2;" : "=f"(lo), "=f"(hi) : "l"(v));
    return make_float2(lo, hi);
}
__device__ __forceinline__ float sigm(float x) {
    return __fdividef(1.f, 1.f + __expf(-x));
}
__device__ __forceinline__ float tanh_f(float x) {
    return __fmaf_rn(2.f, sigm(2.f * x), -1.f);
}
__device__ __forceinline__ uint32_t smem_u32(const void* p) {
    uint32_t a;
    asm("{ .reg .u64 t; cvta.to.shared.u64 t, %1; cvt.u32.u64 %0, t; }" : "=r"(a) : "l"(p));
    return a;
}

// map output column c (0..63) of the big projection to the original W row.
// layout: dir = c>>5, u = (c&31)>>2, gate = (c&31)&3 ; orig row = gate*8 + u
__device__ __forceinline__ int bi_row_of_col(int c, int& dir) {
    dir = c >> 5;
    int w = c & 31;
    return (w & 3) * 8 + (w >> 2);
}

// ---------------- warp MMA (HMMA, plain PTX — works on bare sm_103) ----------------
__device__ __forceinline__ void mma_bf16(float* c, const uint32_t* a, uint32_t b0, uint32_t b1) {
    asm volatile(
        "mma.sync.aligned.m16n8k16.row.col.f32.bf16.bf16.f32 "
        "{%0,%1,%2,%3}, {%4,%5,%6,%7}, {%8,%9}, {%0,%1,%2,%3};"
        : "+f"(c[0]), "+f"(c[1]), "+f"(c[2]), "+f"(c[3])
        : "r"(a[0]), "r"(a[1]), "r"(a[2]), "r"(a[3]), "r"(b0), "r"(b1));
}
__device__ __forceinline__ void ldm4(uint32_t* r, uint32_t addr) {
    asm volatile("ldmatrix.sync.aligned.m8n8.x4.shared.b16 {%0,%1,%2,%3}, [%4];"
                 : "=r"(r[0]), "=r"(r[1]), "=r"(r[2]), "=r"(r[3]) : "r"(addr));
}

// ---------------- K1: HMMA projection GEMM ----------------
// C[R x 64] = X[R x 768] @ Wperm^T + bias, bf16 hi/lo split (3 MMAs), fp32 accum.
// Per CTA: M=128 rows, N=64, K in 12 chunks of 64. 256 threads = 8 warps; warp w
// owns rows 16w..16w+15, all 64 cols (8 n-tiles of 8).
#define PA_HI 0
#define PA_LO 16384
#define PB_HI 32768
#define PB_LO 40960
#define PROJ_SMEM 49152
#define NKC 12

__device__ __forceinline__ void cvt_hilo8(float4 v0, float4 v1, uint4& hi, uint4& lo) {
    float xs[8] = {v0.x, v0.y, v0.z, v0.w, v1.x, v1.y, v1.z, v1.w};
    uint32_t h[4], l[4];
    #pragma unroll
    for (int i = 0; i < 4; i++) {
        float a = xs[2 * i], b = xs[2 * i + 1];
        uint32_t hp;
        asm("cvt.rn.bf16x2.f32 %0, %1, %2;" : "=r"(hp) : "f"(b), "f"(a)); // lo16=a, hi16=b
        float fa = __uint_as_float(hp << 16);
        float fb = __uint_as_float(hp & 0xffff0000u);
        float la = a - fa, lb = b - fb;
        uint32_t lp;
        asm("cvt.rn.bf16x2.f32 %0, %1, %2;" : "=r"(lp) : "f"(lb), "f"(la));
        h[i] = hp; l[i] = lp;
    }
    hi = make_uint4(h[0], h[1], h[2], h[3]);
    lo = make_uint4(l[0], l[1], l[2], l[3]);
}

__global__ void __launch_bounds__(256) proj_mma_kernel(
    const float* __restrict__ X,
    const float* __restrict__ Wf, const float* __restrict__ Wb,
    const float* __restrict__ bif, const float* __restrict__ bhf,
    const float* __restrict__ bib, const float* __restrict__ bhb)
{
    extern __shared__ __align__(1024) char psm[];
    __shared__ float bias[64];
    const uint32_t smem_base = smem_u32(psm);
    const int tid = threadIdx.x;
    const int w = tid >> 5, lane = tid & 31;
    const int row0 = blockIdx.x * 128;

    if (tid < 64) {
        int dir;
        int r = bi_row_of_col(tid, dir);
        bias[tid] = dir ? (bib[r] + bhb[r]) : (bif[r] + bhf[r]);
    }

    // ldmatrix address precompute (swizzle: koffbits ^= (row&7)<<4 within 128B rows)
    const int rowA = 16 * w + (lane & 15);
    const uint32_t aRow = smem_base + rowA * 128;
    const uint32_t axr = (rowA & 7) << 4;
    const uint32_t akoff = (lane >= 16) ? 16u : 0u;

    const int nB = (lane & 7) + ((lane >> 4) << 3);   // 0..15 within a 16-row n-pair block
    const uint32_t bxr = (lane & 7) << 4;
    const uint32_t bkoff = (lane & 8) ? 16u : 0u;

    float acc[32];
    #pragma unroll
    for (int i = 0; i < 32; i++) acc[i] = 0.f;

    for (int kc = 0; kc < NKC; kc++) {
        const int k0 = kc * 64;
        // stage gmem loads into registers (overlaps with previous chunk's MMAs)
        float4 areg[8], breg[4];
        #pragma unroll
        for (int q = 0; q < 4; q++) {
            int unit = tid + q * 256;
            int r = unit >> 3, c8 = unit & 7;
            const float* p = X + (size_t)(row0 + r) * D_ + k0 + c8 * 8;
            areg[2 * q]     = *(const float4*)p;
            areg[2 * q + 1] = *(const float4*)(p + 4);
        }
        #pragma unroll
        for (int q = 0; q < 2; q++) {
            int unit = tid + q * 256;
            int n = unit >> 3, c8 = unit & 7;
            int dir;
            int rr = bi_row_of_col(n, dir);
            const float* p = (dir ? Wb : Wf) + rr * D_ + k0 + c8 * 8;
            breg[2 * q]     = *(const float4*)p;
            breg[2 * q + 1] = *(const float4*)(p + 4);
        }
        __syncthreads();   // previous chunk's ldmatrix reads done before overwrite

        // convert + swizzled store (bf16 hi/lo tiles, 128B rows)
        #pragma unroll
        for (int q = 0; q < 4; q++) {
            int unit = tid + q * 256;
            int r = unit >> 3, c8 = unit & 7;
            uint32_t off = r * 128 + c8 * 16;
            uint32_t sw = off ^ ((off >> 3) & 0x70);
            uint4 hi, lo;
            cvt_hilo8(areg[2 * q], areg[2 * q + 1], hi, lo);
            *(uint4*)(psm + PA_HI + sw) = hi;
            *(uint4*)(psm + PA_LO + sw) = lo;
        }
        #pragma unroll
        for (int q = 0; q < 2; q++) {
            int unit = tid + q * 256;
            int n = unit >> 3, c8 = unit & 7;
            uint32_t off = n * 128 + c8 * 16;
            uint32_t sw = off ^ ((off >> 3) & 0x70);
            uint4 hi, lo;
            cvt_hilo8(breg[2 * q], breg[2 * q + 1], hi, lo);
            *(uint4*)(psm + PB_HI + sw) = hi;
            *(uint4*)(psm + PB_LO + sw) = lo;
        }
        __syncthreads();

        // 4 k-steps of m16n8k16 over 8 n-tiles, hi/lo 3-product split
        #pragma unroll
        for (int ks = 0; ks < 4; ks++) {
            const uint32_t ak = (ks * 32 + akoff) ^ axr;
            uint32_t ahi[4], alo[4];
            ldm4(ahi, aRow + PA_HI + ak);
            ldm4(alo, aRow + PA_LO + ak);
            #pragma unroll
            for (int np = 0; np < 4; np++) {
                const int n = np * 16 + nB;
                const uint32_t bk = (uint32_t)n * 128 + ((ks * 32 + bkoff) ^ bxr);
                uint32_t bhi[4], blo[4];
                ldm4(bhi, smem_base + PB_HI + bk);
                ldm4(blo, smem_base + PB_LO + bk);
                float* c0 = acc + (2 * np) * 4;
                float* c1 = acc + (2 * np + 1) * 4;
                mma_bf16(c0, ahi, bhi[0], bhi[1]);
                mma_bf16(c0, ahi, blo[0], blo[1]);
                mma_bf16(c0, alo, bhi[0], bhi[1]);
                mma_bf16(c1, ahi, bhi[2], bhi[3]);
                mma_bf16(c1, ahi, blo[2], blo[3]);
                mma_bf16(c1, alo, bhi[2], bhi[3]);
            }
        }
    }

    // epilogue: C fragment rows 16w+g / 16w+8+g, cols nt*8 + 2*(lane&3) + {0,1}
    const int g = lane >> 2, tq = (lane & 3) * 2;
    const int r0 = row0 + 16 * w + g;
    #pragma unroll
    for (int nt = 0; nt < 8; nt++) {
        int col = nt * 8 + tq;
        float b0 = bias[col], b1 = bias[col + 1];
        float* d0 = g_xproj + (size_t)r0 * 64 + col;
        float* d1 = g_xproj + (size_t)(r0 + 8) * 64 + col;
        *(float2*)d0 = make_float2(acc[nt * 4 + 0] + b0, acc[nt * 4 + 1] + b1);
        *(float2*)d1 = make_float2(acc[nt * 4 + 2] + b0, acc[nt * 4 + 3] + b1);
    }
}

// ---------------- scan dot helpers ----------------
__device__ __forceinline__ float dot8(ulonglong2 hA, ulonglong2 hB,
                                      ulonglong2 w01, ulonglong2 w23, float x) {
    ull a0 = ffma2(hB.x, w23.x, ffma2(hA.x, w01.x, 0ULL));
    ull a1 = ffma2(hB.y, w23.y, ffma2(hA.y, w01.y, 0ULL));
    float2 v = unpack2(add2(a0, a1));
    return x + v.x + v.y;
}
__device__ __forceinline__ float dot16(ulonglong2 hA, ulonglong2 hB,
                                       ulonglong2 hC, ulonglong2 hD,
                                       ulonglong2 w0, ulonglong2 w1,
                                       ulonglong2 w2, ulonglong2 w3, float x) {
    ull a0 = ffma2(hC.x, w2.x, ffma2(hA.x, w0.x, 0ULL));
    ull a1 = ffma2(hC.y, w2.y, ffma2(hA.y, w0.y, 0ULL));
    ull a2 = ffma2(hD.x, w3.x, ffma2(hB.x, w1.x, 0ULL));
    ull a3 = ffma2(hD.y, w3.y, ffma2(hB.y, w1.y, 0ULL));
    float2 v = unpack2(add2(add2(a0, a1), add2(a2, a3)));
    return x + v.x + v.y;
}

// ---------------- K2: bidirectional LSTM scan (H=8) ----------------
// grid (64, 2), 64 threads = 8 elems x 8 units. Weights in registers,
// h-exchange via double-buffered smem, one float4 gate load/step.
// NOTE: main loop MUST be unrolled by 4 so buf[s&3] stays in registers.
__global__ void __launch_bounds__(64) lstm_bi_kernel(
    const float* __restrict__ Whhf, const float* __restrict__ Whhb)
{
    __shared__ __align__(32) float hsm[2][8][8];
    const int tid = threadIdx.x;
    const int dir = blockIdx.y;
    const int e = tid >> 3, u = tid & 7;
    const int b = blockIdx.x * 8 + e;

    const float* W = dir ? Whhb : Whhf;
    ulonglong2 wi0 = *(const ulonglong2*)(W + u * 8);
    ulonglong2 wi1 = *(const ulonglong2*)(W + u * 8 + 4);
    ulonglong2 wf0 = *(const ulonglong2*)(W + (8 + u) * 8);
    ulonglong2 wf1 = *(const ulonglong2*)(W + (8 + u) * 8 + 4);
    ulonglong2 wg0 = *(const ulonglong2*)(W + (16 + u) * 8);
    ulonglong2 wg1 = *(const ulonglong2*)(W + (16 + u) * 8 + 4);
    ulonglong2 wo0 = *(const ulonglong2*)(W + (24 + u) * 8);
    ulonglong2 wo1 = *(const ulonglong2*)(W + (24 + u) * 8 + 4);

    hsm[0][e][u] = 0.f;
    __syncthreads();
    float cu = 0.f;

    const float4* xsrc = (const float4*)g_xproj;
    const long long stride4 = (long long)B_ * 16;
    const long long step = dir ? -stride4 : stride4;
    long long idx = ((long long)(dir ? T_ - 1 : 0) * B_ + b) * 16 + dir * 8 + u;
    float4 buf[4];
    #pragma unroll
    for (int p = 0; p < 4; p++) buf[p] = xsrc[idx + p * step];

    float* hp0 = g_h + (size_t)b * 16 + dir * 8 + u;

    #pragma unroll 4
    for (int s = 0; s < T_; s++) {
        const int tt = dir ? (T_ - 1 - s) : s;
        float4 x = buf[s & 3];
        if (s + 4 < T_) buf[s & 3] = xsrc[idx + (long long)(s + 4) * step];
        const int p = s & 1;
        ulonglong2 hA = *(const ulonglong2*)&hsm[p][e][0];
        ulonglong2 hB = *(const ulonglong2*)&hsm[p][e][4];

        float gi = dot8(hA, hB, wi0, wi1, x.x);
        float gf = dot8(hA, hB, wf0, wf1, x.y);
        float gg = dot8(hA, hB, wg0, wg1, x.z);
        float go = dot8(hA, hB, wo0, wo1, x.w);

        float ii = sigm(gi), ff = sigm(gf), g2 = tanh_f(gg), oo = sigm(go);
        cu = __fmaf_rn(ff, cu, ii * g2);
        float hu = oo * tanh_f(cu);
        hsm[p ^ 1][e][u] = hu;
        __syncwarp();
        hp0[(size_t)tt * (B_ * 16)] = hu;
    }
}

// ---------------- K3: ptr-LSTM input projection (gate-interleaved output) -------
__global__ void __launch_bounds__(256) zproj_kernel(
    const float* __restrict__ Wihp, const float* __restrict__ bip,
    const float* __restrict__ bhp)
{
    __shared__ float W[64][16];
    __shared__ float bias[64];
    const int tid = threadIdx.x;
    #pragma unroll
    for (int i = tid; i < 1024; i += 256) {
        int n = i >> 4, k = i & 15;
        int u = n >> 2, g = n & 3;
        W[n][k] = Wihp[(g * 16 + u) * 16 + k];
    }
    if (tid < 64) {
        int u = tid >> 2, g = tid & 3;
        int r = g * 16 + u;
        bias[tid] = bip[r] + bhp[r];
    }
    __syncthreads();

    size_t r = (size_t)blockIdx.x * 256 + tid;
    const float4* h4 = (const float4*)(g_h + r * 16);
    float4 a0 = h4[0], a1 = h4[1], a2 = h4[2], a3 = h4[3];
    float hr[16] = {a0.x, a0.y, a0.z, a0.w, a1.x, a1.y, a1.z, a1.w,
                    a2.x, a2.y, a2.z, a2.w, a3.x, a3.y, a3.z, a3.w};
    float* out = g_zproj + r * 64;
    #pragma unroll
    for (int g0 = 0; g0 < 64; g0 += 4) {
        float o[4];
        #pragma unroll
        for (int q = 0; q < 4; q++) {
            int g = g0 + q;
            float a = bias[g];
            #pragma unroll
            for (int k = 0; k < 16; k++) a = __fmaf_rn(W[g][k], hr[k], a);
            o[q] = a;
        }
        *(float4*)(out + g0) = make_float4(o[0], o[1], o[2], o[3]);
    }
}

// ---------------- K4: ptr LSTM scan (H=16) ----------------
// grid 128, 64 threads = 4 elems x 16 units. Weights in registers,
// smem h-exchange, f32x2 dot chains.
// NOTE: main loop MUST be unrolled by 4 so buf[t&3] stays in registers.
__global__ void __launch_bounds__(64) lstm_ptr_kernel(const float* __restrict__ Whhp)
{
    __shared__ __align__(64) float hsm[2][4][16];
    const int tid = threadIdx.x;
    const int e = tid >> 4, u = tid & 15;
    const int b = blockIdx.x * 4 + e;

    ulonglong2 wi[4], wf4[4], wg4[4], wo4[4];
    {
        const ulonglong2* p;
        p = (const ulonglong2*)(Whhp + u * 16);
        wi[0] = p[0]; wi[1] = p[1]; wi[2] = p[2]; wi[3] = p[3];
        p = (const ulonglong2*)(Whhp + (16 + u) * 16);
        wf4[0] = p[0]; wf4[1] = p[1]; wf4[2] = p[2]; wf4[3] = p[3];
        p = (const ulonglong2*)(Whhp + (32 + u) * 16);
        wg4[0] = p[0]; wg4[1] = p[1]; wg4[2] = p[2]; wg4[3] = p[3];
        p = (const ulonglong2*)(Whhp + (48 + u) * 16);
        wo4[0] = p[0]; wo4[1] = p[1]; wo4[2] = p[2]; wo4[3] = p[3];
    }

    hsm[0][e][u] = 0.f;
    __syncthreads();
    float cu = 0.f;

    const float4* zsrc = (const float4*)g_zproj;
    const long long stride4 = (long long)B_ * 16;
    long long idx = (long long)b * 16 + u;
    float4 buf[4];
    #pragma unroll
    for (int p = 0; p < 4; p++) buf[p] = zsrc[idx + p * stride4];

    float* zp0 = g_z + (size_t)b * 16 + u;

    #pragma unroll 4
    for (int t = 0; t < T_; t++) {
        float4 x = buf[t & 3];
        if (t + 4 < T_) buf[t & 3] = zsrc[idx + (long long)(t + 4) * stride4];
        const int p = t & 1;
        const ulonglong2* hr = (const ulonglong2*)&hsm[p][e][0];
        ulonglong2 hA = hr[0], hB = hr[1], hC = hr[2], hD = hr[3];

        float gi = dot16(hA, hB, hC, hD, wi[0], wi[1], wi[2], wi[3], x.x);
        float gf = dot16(hA, hB, hC, hD, wf4[0], wf4[1], wf4[2], wf4[3], x.y);
        float gg = dot16(hA, hB, hC, hD, wg4[0], wg4[1], wg4[2], wg4[3], x.z);
        float go = dot16(hA, hB, hC, hD, wo4[0], wo4[1], wo4[2], wo4[3], x.w);

        float ii = sigm(gi), ff = sigm(gf), g2 = tanh_f(gg), oo = sigm(go);
        cu = __fmaf_rn(ff, cu, ii * g2);
        float hu = oo * tanh_f(cu);
        hsm[p ^ 1][e][u] = hu;
        __syncwarp();
        zp0[(size_t)t * (B_ * 16)] = hu;
    }
}

// ---------------- K5: fused attention + output head, one CTA per t ----------------
#define ATT_SMEM_FLOATS (8192 + 8192 + 512 + 256 + 256 + 16)
__global__ void __launch_bounds__(512) attn_kernel(
    const float* __restrict__ W_h, const float* __restrict__ W_e,
    const float* __restrict__ W_v, float* __restrict__ out)
{
    extern __shared__ __align__(16) float sm[];
    float* hs   = sm;            // 512 x 16
    float* zs   = sm + 8192;     // 512 x 16
    float* cinv = sm + 16384;    // 512
    float* whs  = sm + 16896;    // 16 x 16
    float* wes  = sm + 17152;    // 16 x 16
    float* wvs  = sm + 17408;    // 16

    const int tid = threadIdx.x;
    const int t = blockIdx.x;
    {
        const float4* hsrc = (const float4*)(g_h + (size_t)t * (B_ * 16));
        const float4* zsrc = (const float4*)(g_z + (size_t)t * (B_ * 16));
        float4* hd = (float4*)hs;
        float4* zd = (float4*)zs;
        #pragma unroll
        for (int i = 0; i < 4; i++) {
            hd[tid + i * 512] = hsrc[tid + i * 512];
            zd[tid + i * 512] = zsrc[tid + i * 512];
        }
    }
    if (tid < 256) { whs[tid] = W_h[tid]; wes[tid] = W_e[tid]; }
    if (tid < 16)  wvs[tid] = W_v[tid];
    __syncthreads();

    // ---- pass 1: thread c owns column c -> colsum ----
    {
        const ulonglong2* zr = (const ulonglong2*)(zs + tid * 16);
        ulonglong2 zq0 = zr[0], zq1 = zr[1], zq2 = zr[2], zq3 = zr[3];
        float colsum = 0.f;
        #pragma unroll 2
        for (int bb = 0; bb < B_; bb++) {
            const ulonglong2* hr = (const ulonglong2*)(hs + bb * 16);
            ulonglong2 hq0 = hr[0], hq1 = hr[1], hq2 = hr[2], hq3 = hr[3];
            ull aA = 0ULL, aB = 0ULL;
            aA = ffma2(hq0.x, zq0.x, aA); aB = ffma2(hq0.y, zq0.y, aB);
            aA = ffma2(hq1.x, zq1.x, aA); aB = ffma2(hq1.y, zq1.y, aB);
            aA = ffma2(hq2.x, zq2.x, aA); aB = ffma2(hq2.y, zq2.y, aB);
            aA = ffma2(hq3.x, zq3.x, aA); aB = ffma2(hq3.y, zq3.y, aB);
            float2 va = unpack2(aA), vb = unpack2(aB);
            float S = (va.x + va.y) + (vb.x + vb.y);
            colsum += __expf(S);
        }
        cinv[tid] = __fdividef(1.f, colsum);
    }
    __syncthreads();

    // ---- pass 2 + output head: thread b owns row b ----
    {
        const ulonglong2* hrp = (const ulonglong2*)(hs + tid * 16);
        ulonglong2 hq0 = hrp[0], hq1 = hrp[1], hq2 = hrp[2], hq3 = hrp[3];
        ull cacc[8];
        #pragma unroll
        for (int k = 0; k < 8; k++) cacc[k] = 0ULL;

        #pragma unroll 2
        for (int c = 0; c < B_; c++) {
            const ulonglong2* zr = (const ulonglong2*)(zs + c * 16);
            ulonglong2 zq0 = zr[0], zq1 = zr[1], zq2 = zr[2], zq3 = zr[3];
            ull aA = 0ULL, aB = 0ULL;
            aA = ffma2(hq0.x, zq0.x, aA); aB = ffma2(hq0.y, zq0.y, aB);
            aA = ffma2(hq1.x, zq1.x, aA); aB = ffma2(hq1.y, zq1.y, aB);
            aA = ffma2(hq2.x, zq2.x, aA); aB = ffma2(hq2.y, zq2.y, aB);
            aA = ffma2(hq3.x, zq3.x, aA); aB = ffma2(hq3.y, zq3.y, aB);
            float2 va = unpack2(aA), vb = unpack2(aB);
            float S = (va.x + va.y) + (vb.x + vb.y);
            float w = __expf(S) * cinv[c];
            ull w2 = pack2(w, w);
            const ulonglong2* hc = (const ulonglong2*)(hs + c * 16);
            ulonglong2 hcq0 = hc[0], hcq1 = hc[1], hcq2 = hc[2], hcq3 = hc[3];
            cacc[0] = ffma2(hcq0.x, w2, cacc[0]); cacc[1] = ffma2(hcq0.y, w2, cacc[1]);
            cacc[2] = ffma2(hcq1.x, w2, cacc[2]); cacc[3] = ffma2(hcq1.y, w2, cacc[3]);
            cacc[4] = ffma2(hcq2.x, w2, cacc[4]); cacc[5] = ffma2(hcq2.y, w2, cacc[5]);
            cacc[6] = ffma2(hcq3.x, w2, cacc[6]); cacc[7] = ffma2(hcq3.y, w2, cacc[7]);
        }

        float ctxv[16], hbv[16];
        #pragma unroll
        for (int k = 0; k < 8; k++) {
            float2 v = unpack2(cacc[k]);
            ctxv[2 * k] = v.x; ctxv[2 * k + 1] = v.y;
        }
        {
            float2 v;
            v = unpack2(hq0.x); hbv[0] = v.x;  hbv[1] = v.y;
            v = unpack2(hq0.y); hbv[2] = v.x;  hbv[3] = v.y;
            v = unpack2(hq1.x); hbv[4] = v.x;  hbv[5] = v.y;
            v = unpack2(hq1.y); hbv[6] = v.x;  hbv[7] = v.y;
            v = unpack2(hq2.x); hbv[8] = v.x;  hbv[9] = v.y;
            v = unpack2(hq2.y); hbv[10] = v.x; hbv[11] = v.y;
            v = unpack2(hq3.x); hbv[12] = v.x; hbv[13] = v.y;
            v = unpack2(hq3.y); hbv[14] = v.x; hbv[15] = v.y;
        }
        float pacc = 0.f;
        #pragma unroll
        for (int d = 0; d < 16; d++) {
            float a = 0.f;
            #pragma unroll
            for (int k = 0; k < 16; k++) a = __fmaf_rn(whs[d * 16 + k], hbv[k], a);
            #pragma unroll
            for (int k = 0; k < 16; k++) a = __fmaf_rn(wes[d * 16 + k], ctxv[k], a);
            float ud = tanh_f(a);
            pacc = __fmaf_rn(ud, wvs[d], pacc);
        }
        out[(size_t)t * B_ + tid] = sigm(pacc);
    }
}

// ---------------- launch ----------------
extern "C" void kernel_launch(void* const* d_in, const int* in_sizes, int n_in,
                              void* d_out, int out_size)
{
    (void)in_sizes; (void)n_in; (void)out_size;
    const float* X     = (const float*)d_in[0];
    const float* Wih_f = (const float*)d_in[1];
    const float* Whh_f = (const float*)d_in[2];
    const float* bih_f = (const float*)d_in[3];
    const float* bhh_f = (const float*)d_in[4];
    const float* Wih_b = (const float*)d_in[5];
    const float* Whh_b = (const float*)d_in[6];
    const float* bih_b = (const float*)d_in[7];
    const float* bhh_b = (const float*)d_in[8];
    const float* Wih_p = (const float*)d_in[9];
    const float* Whh_p = (const float*)d_in[10];
    const float* bih_p = (const float*)d_in[11];
    const float* bhh_p = (const float*)d_in[12];
    const float* W_h   = (const float*)d_in[13];
    const float* W_e   = (const float*)d_in[14];
    const float* W_v   = (const float*)d_in[15];
    float* out = (float*)d_out;

    cudaFuncSetAttribute(proj_mma_kernel, cudaFuncAttributeMaxDynamicSharedMemorySize, PROJ_SMEM);
    proj_mma_kernel<<<R_ / 128, 256, PROJ_SMEM>>>(X, Wih_f, Wih_b, bih_f, bhh_f, bih_b, bhh_b);

    lstm_bi_kernel<<<dim3(64, 2), 64>>>(Whh_f, Whh_b);
    zproj_kernel<<<256, 256>>>(Wih_p, bih_p, bhh_p);
    lstm_ptr_kernel<<<128, 64>>>(Whh_p);

    const int att_smem = ATT_SMEM_FLOATS * (int)sizeof(float);  // ~69.7 KB
    cudaFuncSetAttribute(attn_kernel, cudaFuncAttributeMaxDynamicSharedMemorySize, att_smem);
    attn_kernel<<<128, 512, att_smem>>>(W_h, W_e, W_v, out);
}

// round 8
// speedup vs baseline: 1.7455x; 1.0352x over previous
#include <cuda_runtime.h>
#include <cuda_bf16.h>
#include <cstdint>

#define T_ 128
#define B_ 512
#define D_ 768
#define R_ (T_*B_)   // 65536 rows

typedef unsigned long long ull;

// ---------------- scratch (static device globals; no allocation) ----------------
__device__ __align__(16) float g_xproj[R_ * 64];  // [t][b][dir][u][4] : col = dir*32 + u*4 + gate
__device__ __align__(16) float g_h[R_ * 16];      // [t][b][16]: 0..7 fwd h, 8..15 bwd h
__device__ __align__(16) float g_zproj[R_ * 64];  // [t][b][u][4]
__device__ __align__(16) float g_z[R_ * 16];      // ptr-LSTM hidden states

// ---------------- helpers ----------------
__device__ __forceinline__ ull ffma2(ull a, ull b, ull c) {
    ull d;
    asm("fma.rn.f32x2 %0, %1, %2, %3;" : "=l"(d) : "l"(a), "l"(b), "l"(c));
    return d;
}
__device__ __forceinline__ ull add2(ull a, ull b) {
    ull d;
    asm("add.rn.f32x2 %0, %1, %2;" : "=l"(d) : "l"(a), "l"(b));
    return d;
}
__device__ __forceinline__ ull pack2(float lo, float hi) {
    ull r;
    asm("mov.b64 %0, {%1, %2};" : "=l"(r) : "f"(lo), "f"(hi));
    return r;
}
__device__ __forceinline__ float2 unpack2(ull v) {
    float lo, hi;
    asm("mov.b64 {%0, %1}, %2;" : "=f"(lo), "=f"(hi) : "l"(v));
    return make_float2(lo, hi);
}
__device__ __forceinline__ float sigm(float x) {
    return __fdividef(1.f, 1.f + __expf(-x));
}
// HW tanh (MUFU.TANH, sm_75+): single op on the critical path.
__device__ __forceinline__ float tanh_hw(float x) {
    float y;
    asm("tanh.approx.f32 %0, %1;" : "=f"(y) : "f"(x));
    return y;
}
// sigmoid via HW tanh: sigmoid(x) = 0.5*tanh(x/2) + 0.5
__device__ __forceinline__ float sigm_hw(float x) {
    return __fmaf_rn(0.5f, tanh_hw(0.5f * x), 0.5f);
}
__device__ __forceinline__ uint32_t smem_u32(const void* p) {
    uint32_t a;
    asm("{ .reg .u64 t; cvta.to.shared.u64 t, %1; cvt.u32.u64 %0, t; }" : "=r"(a) : "l"(p));
    return a;
}

// map output column c (0..63) of the big projection to the original W row.
// layout: dir = c>>5, u = (c&31)>>2, gate = (c&31)&3 ; orig row = gate*8 + u
__device__ __forceinline__ int bi_row_of_col(int c, int& dir) {
    dir = c >> 5;
    int w = c & 31;
    return (w & 3) * 8 + (w >> 2);
}

// ---------------- warp MMA (HMMA, plain PTX — works on bare sm_103) ----------------
__device__ __forceinline__ void mma_bf16(float* c, const uint32_t* a, uint32_t b0, uint32_t b1) {
    asm volatile(
        "mma.sync.aligned.m16n8k16.row.col.f32.bf16.bf16.f32 "
        "{%0,%1,%2,%3}, {%4,%5,%6,%7}, {%8,%9}, {%0,%1,%2,%3};"
        : "+f"(c[0]), "+f"(c[1]), "+f"(c[2]), "+f"(c[3])
        : "r"(a[0]), "r"(a[1]), "r"(a[2]), "r"(a[3]), "r"(b0), "r"(b1));
}
__device__ __forceinline__ void ldm4(uint32_t* r, uint32_t addr) {
    asm volatile("ldmatrix.sync.aligned.m8n8.x4.shared.b16 {%0,%1,%2,%3}, [%4];"
                 : "=r"(r[0]), "=r"(r[1]), "=r"(r[2]), "=r"(r[3]) : "r"(addr));
}

// ---------------- K1: HMMA projection GEMM ----------------
// C[R x 64] = X[R x 768] @ Wperm^T + bias, bf16 hi/lo split (3 MMAs), fp32 accum.
// Per CTA: M=128 rows, N=64, K in 12 chunks of 64. 256 threads = 8 warps; warp w
// owns rows 16w..16w+15, all 64 cols (8 n-tiles of 8).
#define PA_HI 0
#define PA_LO 16384
#define PB_HI 32768
#define PB_LO 40960
#define PROJ_SMEM 49152
#define NKC 12

__device__ __forceinline__ void cvt_hilo8(float4 v0, float4 v1, uint4& hi, uint4& lo) {
    float xs[8] = {v0.x, v0.y, v0.z, v0.w, v1.x, v1.y, v1.z, v1.w};
    uint32_t h[4], l[4];
    #pragma unroll
    for (int i = 0; i < 4; i++) {
        float a = xs[2 * i], b = xs[2 * i + 1];
        uint32_t hp;
        asm("cvt.rn.bf16x2.f32 %0, %1, %2;" : "=r"(hp) : "f"(b), "f"(a)); // lo16=a, hi16=b
        float fa = __uint_as_float(hp << 16);
        float fb = __uint_as_float(hp & 0xffff0000u);
        float la = a - fa, lb = b - fb;
        uint32_t lp;
        asm("cvt.rn.bf16x2.f32 %0, %1, %2;" : "=r"(lp) : "f"(lb), "f"(la));
        h[i] = hp; l[i] = lp;
    }
    hi = make_uint4(h[0], h[1], h[2], h[3]);
    lo = make_uint4(l[0], l[1], l[2], l[3]);
}

__global__ void __launch_bounds__(256) proj_mma_kernel(
    const float* __restrict__ X,
    const float* __restrict__ Wf, const float* __restrict__ Wb,
    const float* __restrict__ bif, const float* __restrict__ bhf,
    const float* __restrict__ bib, const float* __restrict__ bhb)
{
    extern __shared__ __align__(1024) char psm[];
    __shared__ float bias[64];
    const uint32_t smem_base = smem_u32(psm);
    const int tid = threadIdx.x;
    const int w = tid >> 5, lane = tid & 31;
    const int row0 = blockIdx.x * 128;

    if (tid < 64) {
        int dir;
        int r = bi_row_of_col(tid, dir);
        bias[tid] = dir ? (bib[r] + bhb[r]) : (bif[r] + bhf[r]);
    }

    // ldmatrix address precompute (swizzle: koffbits ^= (row&7)<<4 within 128B rows)
    const int rowA = 16 * w + (lane & 15);
    const uint32_t aRow = smem_base + rowA * 128;
    const uint32_t axr = (rowA & 7) << 4;
    const uint32_t akoff = (lane >= 16) ? 16u : 0u;

    const int nB = (lane & 7) + ((lane >> 4) << 3);   // 0..15 within a 16-row n-pair block
    const uint32_t bxr = (lane & 7) << 4;
    const uint32_t bkoff = (lane & 8) ? 16u : 0u;

    float acc[32];
    #pragma unroll
    for (int i = 0; i < 32; i++) acc[i] = 0.f;

    for (int kc = 0; kc < NKC; kc++) {
        const int k0 = kc * 64;
        // stage gmem loads into registers (overlaps with previous chunk's MMAs)
        float4 areg[8], breg[4];
        #pragma unroll
        for (int q = 0; q < 4; q++) {
            int unit = tid + q * 256;
            int r = unit >> 3, c8 = unit & 7;
            const float* p = X + (size_t)(row0 + r) * D_ + k0 + c8 * 8;
            areg[2 * q]     = *(const float4*)p;
            areg[2 * q + 1] = *(const float4*)(p + 4);
        }
        #pragma unroll
        for (int q = 0; q < 2; q++) {
            int unit = tid + q * 256;
            int n = unit >> 3, c8 = unit & 7;
            int dir;
            int rr = bi_row_of_col(n, dir);
            const float* p = (dir ? Wb : Wf) + rr * D_ + k0 + c8 * 8;
            breg[2 * q]     = *(const float4*)p;
            breg[2 * q + 1] = *(const float4*)(p + 4);
        }
        __syncthreads();   // previous chunk's ldmatrix reads done before overwrite

        // convert + swizzled store (bf16 hi/lo tiles, 128B rows)
        #pragma unroll
        for (int q = 0; q < 4; q++) {
            int unit = tid + q * 256;
            int r = unit >> 3, c8 = unit & 7;
            uint32_t off = r * 128 + c8 * 16;
            uint32_t sw = off ^ ((off >> 3) & 0x70);
            uint4 hi, lo;
            cvt_hilo8(areg[2 * q], areg[2 * q + 1], hi, lo);
            *(uint4*)(psm + PA_HI + sw) = hi;
            *(uint4*)(psm + PA_LO + sw) = lo;
        }
        #pragma unroll
        for (int q = 0; q < 2; q++) {
            int unit = tid + q * 256;
            int n = unit >> 3, c8 = unit & 7;
            uint32_t off = n * 128 + c8 * 16;
            uint32_t sw = off ^ ((off >> 3) & 0x70);
            uint4 hi, lo;
            cvt_hilo8(breg[2 * q], breg[2 * q + 1], hi, lo);
            *(uint4*)(psm + PB_HI + sw) = hi;
            *(uint4*)(psm + PB_LO + sw) = lo;
        }
        __syncthreads();

        // 4 k-steps of m16n8k16 over 8 n-tiles, hi/lo 3-product split
        #pragma unroll
        for (int ks = 0; ks < 4; ks++) {
            const uint32_t ak = (ks * 32 + akoff) ^ axr;
            uint32_t ahi[4], alo[4];
            ldm4(ahi, aRow + PA_HI + ak);
            ldm4(alo, aRow + PA_LO + ak);
            #pragma unroll
            for (int np = 0; np < 4; np++) {
                const int n = np * 16 + nB;
                const uint32_t bk = (uint32_t)n * 128 + ((ks * 32 + bkoff) ^ bxr);
                uint32_t bhi[4], blo[4];
                ldm4(bhi, smem_base + PB_HI + bk);
                ldm4(blo, smem_base + PB_LO + bk);
                float* c0 = acc + (2 * np) * 4;
                float* c1 = acc + (2 * np + 1) * 4;
                mma_bf16(c0, ahi, bhi[0], bhi[1]);
                mma_bf16(c0, ahi, blo[0], blo[1]);
                mma_bf16(c0, alo, bhi[0], bhi[1]);
                mma_bf16(c1, ahi, bhi[2], bhi[3]);
                mma_bf16(c1, ahi, blo[2], blo[3]);
                mma_bf16(c1, alo, bhi[2], bhi[3]);
            }
        }
    }

    // epilogue: C fragment rows 16w+g / 16w+8+g, cols nt*8 + 2*(lane&3) + {0,1}
    const int g = lane >> 2, tq = (lane & 3) * 2;
    const int r0 = row0 + 16 * w + g;
    #pragma unroll
    for (int nt = 0; nt < 8; nt++) {
        int col = nt * 8 + tq;
        float b0 = bias[col], b1 = bias[col + 1];
        float* d0 = g_xproj + (size_t)r0 * 64 + col;
        float* d1 = g_xproj + (size_t)(r0 + 8) * 64 + col;
        *(float2*)d0 = make_float2(acc[nt * 4 + 0] + b0, acc[nt * 4 + 1] + b1);
        *(float2*)d1 = make_float2(acc[nt * 4 + 2] + b0, acc[nt * 4 + 3] + b1);
    }
}

// ---------------- scan dot helpers ----------------
__device__ __forceinline__ float dot8(ulonglong2 hA, ulonglong2 hB,
                                      ulonglong2 w01, ulonglong2 w23, float x) {
    ull a0 = ffma2(hB.x, w23.x, ffma2(hA.x, w01.x, 0ULL));
    ull a1 = ffma2(hB.y, w23.y, ffma2(hA.y, w01.y, 0ULL));
    float2 v = unpack2(add2(a0, a1));
    return x + v.x + v.y;
}
__device__ __forceinline__ float dot16(ulonglong2 hA, ulonglong2 hB,
                                       ulonglong2 hC, ulonglong2 hD,
                                       ulonglong2 w0, ulonglong2 w1,
                                       ulonglong2 w2, ulonglong2 w3, float x) {
    ull a0 = ffma2(hC.x, w2.x, ffma2(hA.x, w0.x, 0ULL));
    ull a1 = ffma2(hC.y, w2.y, ffma2(hA.y, w0.y, 0ULL));
    ull a2 = ffma2(hD.x, w3.x, ffma2(hB.x, w1.x, 0ULL));
    ull a3 = ffma2(hD.y, w3.y, ffma2(hB.y, w1.y, 0ULL));
    float2 v = unpack2(add2(add2(a0, a1), add2(a2, a3)));
    return x + v.x + v.y;
}

// ---------------- K2: bidirectional LSTM scan (H=8) ----------------
// grid (64, 2), 64 threads = 8 elems x 8 units. Weights in registers,
// h-exchange via double-buffered smem, one float4 gate load/step.
// NOTE: main loop MUST be unrolled by 4 so buf[s&3] stays in registers.
__global__ void __launch_bounds__(64) lstm_bi_kernel(
    const float* __restrict__ Whhf, const float* __restrict__ Whhb)
{
    __shared__ __align__(32) float hsm[2][8][8];
    const int tid = threadIdx.x;
    const int dir = blockIdx.y;
    const int e = tid >> 3, u = tid & 7;
    const int b = blockIdx.x * 8 + e;

    const float* W = dir ? Whhb : Whhf;
    ulonglong2 wi0 = *(const ulonglong2*)(W + u * 8);
    ulonglong2 wi1 = *(const ulonglong2*)(W + u * 8 + 4);
    ulonglong2 wf0 = *(const ulonglong2*)(W + (8 + u) * 8);
    ulonglong2 wf1 = *(const ulonglong2*)(W + (8 + u) * 8 + 4);
    ulonglong2 wg0 = *(const ulonglong2*)(W + (16 + u) * 8);
    ulonglong2 wg1 = *(const ulonglong2*)(W + (16 + u) * 8 + 4);
    ulonglong2 wo0 = *(const ulonglong2*)(W + (24 + u) * 8);
    ulonglong2 wo1 = *(const ulonglong2*)(W + (24 + u) * 8 + 4);

    hsm[0][e][u] = 0.f;
    __syncthreads();
    float cu = 0.f;

    const float4* xsrc = (const float4*)g_xproj;
    const long long stride4 = (long long)B_ * 16;
    const long long step = dir ? -stride4 : stride4;
    long long idx = ((long long)(dir ? T_ - 1 : 0) * B_ + b) * 16 + dir * 8 + u;
    float4 buf[4];
    #pragma unroll
    for (int p = 0; p < 4; p++) buf[p] = xsrc[idx + p * step];

    float* hp0 = g_h + (size_t)b * 16 + dir * 8 + u;

    #pragma unroll 4
    for (int s = 0; s < T_; s++) {
        const int tt = dir ? (T_ - 1 - s) : s;
        float4 x = buf[s & 3];
        if (s + 4 < T_) buf[s & 3] = xsrc[idx + (long long)(s + 4) * step];
        const int p = s & 1;
        ulonglong2 hA = *(const ulonglong2*)&hsm[p][e][0];
        ulonglong2 hB = *(const ulonglong2*)&hsm[p][e][4];

        float gi = dot8(hA, hB, wi0, wi1, x.x);
        float gf = dot8(hA, hB, wf0, wf1, x.y);
        float gg = dot8(hA, hB, wg0, wg1, x.z);
        float go = dot8(hA, hB, wo0, wo1, x.w);

        float ii = sigm_hw(gi), ff = sigm_hw(gf);
        float g2 = tanh_hw(gg), oo = sigm_hw(go);
        cu = __fmaf_rn(ff, cu, ii * g2);
        float hu = oo * tanh_hw(cu);
        hsm[p ^ 1][e][u] = hu;
        __syncwarp();
        hp0[(size_t)tt * (B_ * 16)] = hu;
    }
}

// ---------------- K3: ptr-LSTM input projection (gate-interleaved output) -------
__global__ void __launch_bounds__(256) zproj_kernel(
    const float* __restrict__ Wihp, const float* __restrict__ bip,
    const float* __restrict__ bhp)
{
    __shared__ float W[64][16];
    __shared__ float bias[64];
    const int tid = threadIdx.x;
    #pragma unroll
    for (int i = tid; i < 1024; i += 256) {
        int n = i >> 4, k = i & 15;
        int u = n >> 2, g = n & 3;
        W[n][k] = Wihp[(g * 16 + u) * 16 + k];
    }
    if (tid < 64) {
        int u = tid >> 2, g = tid & 3;
        int r = g * 16 + u;
        bias[tid] = bip[r] + bhp[r];
    }
    __syncthreads();

    size_t r = (size_t)blockIdx.x * 256 + tid;
    const float4* h4 = (const float4*)(g_h + r * 16);
    float4 a0 = h4[0], a1 = h4[1], a2 = h4[2], a3 = h4[3];
    float hr[16] = {a0.x, a0.y, a0.z, a0.w, a1.x, a1.y, a1.z, a1.w,
                    a2.x, a2.y, a2.z, a2.w, a3.x, a3.y, a3.z, a3.w};
    float* out = g_zproj + r * 64;
    #pragma unroll
    for (int g0 = 0; g0 < 64; g0 += 4) {
        float o[4];
        #pragma unroll
        for (int q = 0; q < 4; q++) {
            int g = g0 + q;
            float a = bias[g];
            #pragma unroll
            for (int k = 0; k < 16; k++) a = __fmaf_rn(W[g][k], hr[k], a);
            o[q] = a;
        }
        *(float4*)(out + g0) = make_float4(o[0], o[1], o[2], o[3]);
    }
}

// ---------------- K4: ptr LSTM scan (H=16) ----------------
// grid 128, 64 threads = 4 elems x 16 units. Weights in registers,
// smem h-exchange, f32x2 dot chains, HW tanh activations.
// NOTE: main loop MUST be unrolled by 4 so buf[t&3] stays in registers.
__global__ void __launch_bounds__(64) lstm_ptr_kernel(const float* __restrict__ Whhp)
{
    __shared__ __align__(64) float hsm[2][4][16];
    const int tid = threadIdx.x;
    const int e = tid >> 4, u = tid & 15;
    const int b = blockIdx.x * 4 + e;

    ulonglong2 wi[4], wf4[4], wg4[4], wo4[4];
    {
        const ulonglong2* p;
        p = (const ulonglong2*)(Whhp + u * 16);
        wi[0] = p[0]; wi[1] = p[1]; wi[2] = p[2]; wi[3] = p[3];
        p = (const ulonglong2*)(Whhp + (16 + u) * 16);
        wf4[0] = p[0]; wf4[1] = p[1]; wf4[2] = p[2]; wf4[3] = p[3];
        p = (const ulonglong2*)(Whhp + (32 + u) * 16);
        wg4[0] = p[0]; wg4[1] = p[1]; wg4[2] = p[2]; wg4[3] = p[3];
        p = (const ulonglong2*)(Whhp + (48 + u) * 16);
        wo4[0] = p[0]; wo4[1] = p[1]; wo4[2] = p[2]; wo4[3] = p[3];
    }

    hsm[0][e][u] = 0.f;
    __syncthreads();
    float cu = 0.f;

    const float4* zsrc = (const float4*)g_zproj;
    const long long stride4 = (long long)B_ * 16;
    long long idx = (long long)b * 16 + u;
    float4 buf[4];
    #pragma unroll
    for (int p = 0; p < 4; p++) buf[p] = zsrc[idx + p * stride4];

    float* zp0 = g_z + (size_t)b * 16 + u;

    #pragma unroll 4
    for (int t = 0; t < T_; t++) {
        float4 x = buf[t & 3];
        if (t + 4 < T_) buf[t & 3] = zsrc[idx + (long long)(t + 4) * stride4];
        const int p = t & 1;
        const ulonglong2* hr = (const ulonglong2*)&hsm[p][e][0];
        ulonglong2 hA = hr[0], hB = hr[1], hC = hr[2], hD = hr[3];

        float gi = dot16(hA, hB, hC, hD, wi[0], wi[1], wi[2], wi[3], x.x);
        float gf = dot16(hA, hB, hC, hD, wf4[0], wf4[1], wf4[2], wf4[3], x.y);
        float gg = dot16(hA, hB, hC, hD, wg4[0], wg4[1], wg4[2], wg4[3], x.z);
        float go = dot16(hA, hB, hC, hD, wo4[0], wo4[1], wo4[2], wo4[3], x.w);

        float ii = sigm_hw(gi), ff = sigm_hw(gf);
        float g2 = tanh_hw(gg), oo = sigm_hw(go);
        cu = __fmaf_rn(ff, cu, ii * g2);
        float hu = oo * tanh_hw(cu);
        hsm[p ^ 1][e][u] = hu;
        __syncwarp();
        zp0[(size_t)t * (B_ * 16)] = hu;
    }
}

// ---------------- K5: fused attention + output head, one CTA per t ----------------
#define ATT_SMEM_FLOATS (8192 + 8192 + 512 + 256 + 256 + 16)
__global__ void __launch_bounds__(512) attn_kernel(
    const float* __restrict__ W_h, const float* __restrict__ W_e,
    const float* __restrict__ W_v, float* __restrict__ out)
{
    extern __shared__ __align__(16) float sm[];
    float* hs   = sm;            // 512 x 16
    float* zs   = sm + 8192;     // 512 x 16
    float* cinv = sm + 16384;    // 512
    float* whs  = sm + 16896;    // 16 x 16
    float* wes  = sm + 17152;    // 16 x 16
    float* wvs  = sm + 17408;    // 16

    const int tid = threadIdx.x;
    const int t = blockIdx.x;
    {
        const float4* hsrc = (const float4*)(g_h + (size_t)t * (B_ * 16));
        const float4* zsrc = (const float4*)(g_z + (size_t)t * (B_ * 16));
        float4* hd = (float4*)hs;
        float4* zd = (float4*)zs;
        #pragma unroll
        for (int i = 0; i < 4; i++) {
            hd[tid + i * 512] = hsrc[tid + i * 512];
            zd[tid + i * 512] = zsrc[tid + i * 512];
        }
    }
    if (tid < 256) { whs[tid] = W_h[tid]; wes[tid] = W_e[tid]; }
    if (tid < 16)  wvs[tid] = W_v[tid];
    __syncthreads();

    // ---- pass 1: thread c owns column c -> colsum ----
    {
        const ulonglong2* zr = (const ulonglong2*)(zs + tid * 16);
        ulonglong2 zq0 = zr[0], zq1 = zr[1], zq2 = zr[2], zq3 = zr[3];
        float colsum = 0.f;
        #pragma unroll 2
        for (int bb = 0; bb < B_; bb++) {
            const ulonglong2* hr = (const ulonglong2*)(hs + bb * 16);
            ulonglong2 hq0 = hr[0], hq1 = hr[1], hq2 = hr[2], hq3 = hr[3];
            ull aA = 0ULL, aB = 0ULL;
            aA = ffma2(hq0.x, zq0.x, aA); aB = ffma2(hq0.y, zq0.y, aB);
            aA = ffma2(hq1.x, zq1.x, aA); aB = ffma2(hq1.y, zq1.y, aB);
            aA = ffma2(hq2.x, zq2.x, aA); aB = ffma2(hq2.y, zq2.y, aB);
            aA = ffma2(hq3.x, zq3.x, aA); aB = ffma2(hq3.y, zq3.y, aB);
            float2 va = unpack2(aA), vb = unpack2(aB);
            float S = (va.x + va.y) + (vb.x + vb.y);
            colsum += __expf(S);
        }
        cinv[tid] = __fdividef(1.f, colsum);
    }
    __syncthreads();

    // ---- pass 2 + output head: thread b owns row b ----
    {
        const ulonglong2* hrp = (const ulonglong2*)(hs + tid * 16);
        ulonglong2 hq0 = hrp[0], hq1 = hrp[1], hq2 = hrp[2], hq3 = hrp[3];
        ull cacc[8];
        #pragma unroll
        for (int k = 0; k < 8; k++) cacc[k] = 0ULL;

        #pragma unroll 2
        for (int c = 0; c < B_; c++) {
            const ulonglong2* zr = (const ulonglong2*)(zs + c * 16);
            ulonglong2 zq0 = zr[0], zq1 = zr[1], zq2 = zr[2], zq3 = zr[3];
            ull aA = 0ULL, aB = 0ULL;
            aA = ffma2(hq0.x, zq0.x, aA); aB = ffma2(hq0.y, zq0.y, aB);
            aA = ffma2(hq1.x, zq1.x, aA); aB = ffma2(hq1.y, zq1.y, aB);
            aA = ffma2(hq2.x, zq2.x, aA); aB = ffma2(hq2.y, zq2.y, aB);
            aA = ffma2(hq3.x, zq3.x, aA); aB = ffma2(hq3.y, zq3.y, aB);
            float2 va = unpack2(aA), vb = unpack2(aB);
            float S = (va.x + va.y) + (vb.x + vb.y);
            float w = __expf(S) * cinv[c];
            ull w2 = pack2(w, w);
            const ulonglong2* hc = (const ulonglong2*)(hs + c * 16);
            ulonglong2 hcq0 = hc[0], hcq1 = hc[1], hcq2 = hc[2], hcq3 = hc[3];
            cacc[0] = ffma2(hcq0.x, w2, cacc[0]); cacc[1] = ffma2(hcq0.y, w2, cacc[1]);
            cacc[2] = ffma2(hcq1.x, w2, cacc[2]); cacc[3] = ffma2(hcq1.y, w2, cacc[3]);
            cacc[4] = ffma2(hcq2.x, w2, cacc[4]); cacc[5] = ffma2(hcq2.y, w2, cacc[5]);
            cacc[6] = ffma2(hcq3.x, w2, cacc[6]); cacc[7] = ffma2(hcq3.y, w2, cacc[7]);
        }

        float ctxv[16], hbv[16];
        #pragma unroll
        for (int k = 0; k < 8; k++) {
            float2 v = unpack2(cacc[k]);
            ctxv[2 * k] = v.x; ctxv[2 * k + 1] = v.y;
        }
        {
            float2 v;
            v = unpack2(hq0.x); hbv[0] = v.x;  hbv[1] = v.y;
            v = unpack2(hq0.y); hbv[2] = v.x;  hbv[3] = v.y;
            v = unpack2(hq1.x); hbv[4] = v.x;  hbv[5] = v.y;
            v = unpack2(hq1.y); hbv[6] = v.x;  hbv[7] = v.y;
            v = unpack2(hq2.x); hbv[8] = v.x;  hbv[9] = v.y;
            v = unpack2(hq2.y); hbv[10] = v.x; hbv[11] = v.y;
            v = unpack2(hq3.x); hbv[12] = v.x; hbv[13] = v.y;
            v = unpack2(hq3.y); hbv[14] = v.x; hbv[15] = v.y;
        }
        float pacc = 0.f;
        #pragma unroll
        for (int d = 0; d < 16; d++) {
            float a = 0.f;
            #pragma unroll
            for (int k = 0; k < 16; k++) a = __fmaf_rn(whs[d * 16 + k], hbv[k], a);
            #pragma unroll
            for (int k = 0; k < 16; k++) a = __fmaf_rn(wes[d * 16 + k], ctxv[k], a);
            float ud = tanh_hw(a);
            pacc = __fmaf_rn(ud, wvs[d], pacc);
        }
        out[(size_t)t * B_ + tid] = sigm_hw(pacc);
    }
}

// ---------------- launch ----------------
extern "C" void kernel_launch(void* const* d_in, const int* in_sizes, int n_in,
                              void* d_out, int out_size)
{
    (void)in_sizes; (void)n_in; (void)out_size;
    const float* X     = (const float*)d_in[0];
    const float* Wih_f = (const float*)d_in[1];
    const float* Whh_f = (const float*)d_in[2];
    const float* bih_f = (const float*)d_in[3];
    const float* bhh_f = (const float*)d_in[4];
    const float* Wih_b = (const float*)d_in[5];
    const float* Whh_b = (const float*)d_in[6];
    const float* bih_b = (const float*)d_in[7];
    const float* bhh_b = (const float*)d_in[8];
    const float* Wih_p = (const float*)d_in[9];
    const float* Whh_p = (const float*)d_in[10];
    const float* bih_p = (const float*)d_in[11];
    const float* bhh_p = (const float*)d_in[12];
    const float* W_h   = (const float*)d_in[13];
    const float* W_e   = (const float*)d_in[14];
    const float* W_v   = (const float*)d_in[15];
    float* out = (float*)d_out;

    cudaFuncSetAttribute(proj_mma_kernel, cudaFuncAttributeMaxDynamicSharedMemorySize, PROJ_SMEM);
    proj_mma_kernel<<<R_ / 128, 256, PROJ_SMEM>>>(X, Wih_f, Wih_b, bih_f, bhh_f, bih_b, bhh_b);

    lstm_bi_kernel<<<dim3(64, 2), 64>>>(Whh_f, Whh_b);
    zproj_kernel<<<256, 256>>>(Wih_p, bih_p, bhh_p);
    lstm_ptr_kernel<<<128, 64>>>(Whh_p);

    const int att_smem = ATT_SMEM_FLOATS * (int)sizeof(float);  // ~69.7 KB
    cudaFuncSetAttribute(attn_kernel, cudaFuncAttributeMaxDynamicSharedMemorySize, att_smem);
    attn_kernel<<<128, 512, att_smem>>>(W_h, W_e, W_v, out);
}

// round 9
// speedup vs baseline: 1.8187x; 1.0419x over previous
#include <cuda_runtime.h>
#include <cuda_bf16.h>
#include <cstdint>

#define T_ 128
#define B_ 512
#define D_ 768
#define R_ (T_*B_)   // 65536 rows

typedef unsigned long long ull;

// ---------------- scratch (static device globals; no allocation) ----------------
__device__ __align__(16) float g_xproj[R_ * 64];  // [t][b][dir][u][4] : col = dir*32 + u*4 + gate
__device__ __align__(16) float g_h[R_ * 16];      // [t][b][16]: 0..7 fwd h, 8..15 bwd h
__device__ __align__(16) float g_zproj[R_ * 64];  // [t][b][u][4]
__device__ __align__(16) float g_z[R_ * 16];      // ptr-LSTM hidden states
__device__ __align__(16) __nv_bfloat16 g_eb[(size_t)T_ * B_ * B_];  // exp(S) cache, 67MB

// ---------------- helpers ----------------
__device__ __forceinline__ ull ffma2(ull a, ull b, ull c) {
    ull d;
    asm("fma.rn.f32x2 %0, %1, %2, %3;" : "=l"(d) : "l"(a), "l"(b), "l"(c));
    return d;
}
__device__ __forceinline__ ull add2(ull a, ull b) {
    ull d;
    asm("add.rn.f32x2 %0, %1, %2;" : "=l"(d) : "l"(a), "l"(b));
    return d;
}
__device__ __forceinline__ ull pack2(float lo, float hi) {
    ull r;
    asm("mov.b64 %0, {%1, %2};" : "=l"(r) : "f"(lo), "f"(hi));
    return r;
}
__device__ __forceinline__ float2 unpack2(ull v) {
    float lo, hi;
    asm("mov.b64 {%0, %1}, %2;" : "=f"(lo), "=f"(hi) : "l"(v));
    return make_float2(lo, hi);
}
// HW tanh (MUFU.TANH, sm_75+): single op on the critical path.
__device__ __forceinline__ float tanh_hw(float x) {
    float y;
    asm("tanh.approx.f32 %0, %1;" : "=f"(y) : "f"(x));
    return y;
}
// sigmoid via HW tanh: sigmoid(x) = 0.5*tanh(x/2) + 0.5
__device__ __forceinline__ float sigm_hw(float x) {
    return __fmaf_rn(0.5f, tanh_hw(0.5f * x), 0.5f);
}
__device__ __forceinline__ float ex2(float x) {
    float y;
    asm("ex2.approx.f32 %0, %1;" : "=f"(y) : "f"(x));
    return y;
}
__device__ __forceinline__ uint32_t smem_u32(const void* p) {
    uint32_t a;
    asm("{ .reg .u64 t; cvta.to.shared.u64 t, %1; cvt.u32.u64 %0, t; }" : "=r"(a) : "l"(p));
    return a;
}

// map output column c (0..63) of the big projection to the original W row.
// layout: dir = c>>5, u = (c&31)>>2, gate = (c&31)&3 ; orig row = gate*8 + u
__device__ __forceinline__ int bi_row_of_col(int c, int& dir) {
    dir = c >> 5;
    int w = c & 31;
    return (w & 3) * 8 + (w >> 2);
}

// ---------------- warp MMA (HMMA, plain PTX — works on bare sm_103) ----------------
__device__ __forceinline__ void mma_bf16(float* c, const uint32_t* a, uint32_t b0, uint32_t b1) {
    asm volatile(
        "mma.sync.aligned.m16n8k16.row.col.f32.bf16.bf16.f32 "
        "{%0,%1,%2,%3}, {%4,%5,%6,%7}, {%8,%9}, {%0,%1,%2,%3};"
        : "+f"(c[0]), "+f"(c[1]), "+f"(c[2]), "+f"(c[3])
        : "r"(a[0]), "r"(a[1]), "r"(a[2]), "r"(a[3]), "r"(b0), "r"(b1));
}
__device__ __forceinline__ void ldm4(uint32_t* r, uint32_t addr) {
    asm volatile("ldmatrix.sync.aligned.m8n8.x4.shared.b16 {%0,%1,%2,%3}, [%4];"
                 : "=r"(r[0]), "=r"(r[1]), "=r"(r[2]), "=r"(r[3]) : "r"(addr));
}

// ---------------- K1: HMMA projection GEMM ----------------
// C[R x 64] = X[R x 768] @ Wperm^T + bias, bf16 hi/lo split (3 MMAs), fp32 accum.
#define PA_HI 0
#define PA_LO 16384
#define PB_HI 32768
#define PB_LO 40960
#define PROJ_SMEM 49152
#define NKC 12

__device__ __forceinline__ void cvt_hilo8(float4 v0, float4 v1, uint4& hi, uint4& lo) {
    float xs[8] = {v0.x, v0.y, v0.z, v0.w, v1.x, v1.y, v1.z, v1.w};
    uint32_t h[4], l[4];
    #pragma unroll
    for (int i = 0; i < 4; i++) {
        float a = xs[2 * i], b = xs[2 * i + 1];
        uint32_t hp;
        asm("cvt.rn.bf16x2.f32 %0, %1, %2;" : "=r"(hp) : "f"(b), "f"(a)); // lo16=a, hi16=b
        float fa = __uint_as_float(hp << 16);
        float fb = __uint_as_float(hp & 0xffff0000u);
        float la = a - fa, lb = b - fb;
        uint32_t lp;
        asm("cvt.rn.bf16x2.f32 %0, %1, %2;" : "=r"(lp) : "f"(lb), "f"(la));
        h[i] = hp; l[i] = lp;
    }
    hi = make_uint4(h[0], h[1], h[2], h[3]);
    lo = make_uint4(l[0], l[1], l[2], l[3]);
}

__global__ void __launch_bounds__(256) proj_mma_kernel(
    const float* __restrict__ X,
    const float* __restrict__ Wf, const float* __restrict__ Wb,
    const float* __restrict__ bif, const float* __restrict__ bhf,
    const float* __restrict__ bib, const float* __restrict__ bhb)
{
    extern __shared__ __align__(1024) char psm[];
    __shared__ float bias[64];
    const uint32_t smem_base = smem_u32(psm);
    const int tid = threadIdx.x;
    const int w = tid >> 5, lane = tid & 31;
    const int row0 = blockIdx.x * 128;

    if (tid < 64) {
        int dir;
        int r = bi_row_of_col(tid, dir);
        bias[tid] = dir ? (bib[r] + bhb[r]) : (bif[r] + bhf[r]);
    }

    const int rowA = 16 * w + (lane & 15);
    const uint32_t aRow = smem_base + rowA * 128;
    const uint32_t axr = (rowA & 7) << 4;
    const uint32_t akoff = (lane >= 16) ? 16u : 0u;

    const int nB = (lane & 7) + ((lane >> 4) << 3);
    const uint32_t bxr = (lane & 7) << 4;
    const uint32_t bkoff = (lane & 8) ? 16u : 0u;

    float acc[32];
    #pragma unroll
    for (int i = 0; i < 32; i++) acc[i] = 0.f;

    for (int kc = 0; kc < NKC; kc++) {
        const int k0 = kc * 64;
        float4 areg[8], breg[4];
        #pragma unroll
        for (int q = 0; q < 4; q++) {
            int unit = tid + q * 256;
            int r = unit >> 3, c8 = unit & 7;
            const float* p = X + (size_t)(row0 + r) * D_ + k0 + c8 * 8;
            areg[2 * q]     = *(const float4*)p;
            areg[2 * q + 1] = *(const float4*)(p + 4);
        }
        #pragma unroll
        for (int q = 0; q < 2; q++) {
            int unit = tid + q * 256;
            int n = unit >> 3, c8 = unit & 7;
            int dir;
            int rr = bi_row_of_col(n, dir);
            const float* p = (dir ? Wb : Wf) + rr * D_ + k0 + c8 * 8;
            breg[2 * q]     = *(const float4*)p;
            breg[2 * q + 1] = *(const float4*)(p + 4);
        }
        __syncthreads();

        #pragma unroll
        for (int q = 0; q < 4; q++) {
            int unit = tid + q * 256;
            int r = unit >> 3, c8 = unit & 7;
            uint32_t off = r * 128 + c8 * 16;
            uint32_t sw = off ^ ((off >> 3) & 0x70);
            uint4 hi, lo;
            cvt_hilo8(areg[2 * q], areg[2 * q + 1], hi, lo);
            *(uint4*)(psm + PA_HI + sw) = hi;
            *(uint4*)(psm + PA_LO + sw) = lo;
        }
        #pragma unroll
        for (int q = 0; q < 2; q++) {
            int unit = tid + q * 256;
            int n = unit >> 3, c8 = unit & 7;
            uint32_t off = n * 128 + c8 * 16;
            uint32_t sw = off ^ ((off >> 3) & 0x70);
            uint4 hi, lo;
            cvt_hilo8(breg[2 * q], breg[2 * q + 1], hi, lo);
            *(uint4*)(psm + PB_HI + sw) = hi;
            *(uint4*)(psm + PB_LO + sw) = lo;
        }
        __syncthreads();

        #pragma unroll
        for (int ks = 0; ks < 4; ks++) {
            const uint32_t ak = (ks * 32 + akoff) ^ axr;
            uint32_t ahi[4], alo[4];
            ldm4(ahi, aRow + PA_HI + ak);
            ldm4(alo, aRow + PA_LO + ak);
            #pragma unroll
            for (int np = 0; np < 4; np++) {
                const int n = np * 16 + nB;
                const uint32_t bk = (uint32_t)n * 128 + ((ks * 32 + bkoff) ^ bxr);
                uint32_t bhi[4], blo[4];
                ldm4(bhi, smem_base + PB_HI + bk);
                ldm4(blo, smem_base + PB_LO + bk);
                float* c0 = acc + (2 * np) * 4;
                float* c1 = acc + (2 * np + 1) * 4;
                mma_bf16(c0, ahi, bhi[0], bhi[1]);
                mma_bf16(c0, ahi, blo[0], blo[1]);
                mma_bf16(c0, alo, bhi[0], bhi[1]);
                mma_bf16(c1, ahi, bhi[2], bhi[3]);
                mma_bf16(c1, ahi, blo[2], blo[3]);
                mma_bf16(c1, alo, bhi[2], bhi[3]);
            }
        }
    }

    const int g = lane >> 2, tq = (lane & 3) * 2;
    const int r0 = row0 + 16 * w + g;
    #pragma unroll
    for (int nt = 0; nt < 8; nt++) {
        int col = nt * 8 + tq;
        float b0 = bias[col], b1 = bias[col + 1];
        float* d0 = g_xproj + (size_t)r0 * 64 + col;
        float* d1 = g_xproj + (size_t)(r0 + 8) * 64 + col;
        *(float2*)d0 = make_float2(acc[nt * 4 + 0] + b0, acc[nt * 4 + 1] + b1);
        *(float2*)d1 = make_float2(acc[nt * 4 + 2] + b0, acc[nt * 4 + 3] + b1);
    }
}

// ---------------- scan dot helpers ----------------
__device__ __forceinline__ float dot8(ulonglong2 hA, ulonglong2 hB,
                                      ulonglong2 w01, ulonglong2 w23, float x) {
    ull a0 = ffma2(hB.x, w23.x, ffma2(hA.x, w01.x, 0ULL));
    ull a1 = ffma2(hB.y, w23.y, ffma2(hA.y, w01.y, 0ULL));
    float2 v = unpack2(add2(a0, a1));
    return x + v.x + v.y;
}
__device__ __forceinline__ float dot16(ulonglong2 hA, ulonglong2 hB,
                                       ulonglong2 hC, ulonglong2 hD,
                                       ulonglong2 w0, ulonglong2 w1,
                                       ulonglong2 w2, ulonglong2 w3, float x) {
    ull a0 = ffma2(hC.x, w2.x, ffma2(hA.x, w0.x, 0ULL));
    ull a1 = ffma2(hC.y, w2.y, ffma2(hA.y, w0.y, 0ULL));
    ull a2 = ffma2(hD.x, w3.x, ffma2(hB.x, w1.x, 0ULL));
    ull a3 = ffma2(hD.y, w3.y, ffma2(hB.y, w1.y, 0ULL));
    float2 v = unpack2(add2(add2(a0, a1), add2(a2, a3)));
    return x + v.x + v.y;
}

// ---------------- K2: bidirectional LSTM scan (H=8) ----------------
__global__ void __launch_bounds__(64) lstm_bi_kernel(
    const float* __restrict__ Whhf, const float* __restrict__ Whhb)
{
    __shared__ __align__(32) float hsm[2][8][8];
    const int tid = threadIdx.x;
    const int dir = blockIdx.y;
    const int e = tid >> 3, u = tid & 7;
    const int b = blockIdx.x * 8 + e;

    const float* W = dir ? Whhb : Whhf;
    ulonglong2 wi0 = *(const ulonglong2*)(W + u * 8);
    ulonglong2 wi1 = *(const ulonglong2*)(W + u * 8 + 4);
    ulonglong2 wf0 = *(const ulonglong2*)(W + (8 + u) * 8);
    ulonglong2 wf1 = *(const ulonglong2*)(W + (8 + u) * 8 + 4);
    ulonglong2 wg0 = *(const ulonglong2*)(W + (16 + u) * 8);
    ulonglong2 wg1 = *(const ulonglong2*)(W + (16 + u) * 8 + 4);
    ulonglong2 wo0 = *(const ulonglong2*)(W + (24 + u) * 8);
    ulonglong2 wo1 = *(const ulonglong2*)(W + (24 + u) * 8 + 4);

    hsm[0][e][u] = 0.f;
    __syncthreads();
    float cu = 0.f;

    const float4* xsrc = (const float4*)g_xproj;
    const long long stride4 = (long long)B_ * 16;
    const long long step = dir ? -stride4 : stride4;
    long long idx = ((long long)(dir ? T_ - 1 : 0) * B_ + b) * 16 + dir * 8 + u;
    float4 buf[4];
    #pragma unroll
    for (int p = 0; p < 4; p++) buf[p] = xsrc[idx + p * step];

    float* hp0 = g_h + (size_t)b * 16 + dir * 8 + u;

    #pragma unroll 4
    for (int s = 0; s < T_; s++) {
        const int tt = dir ? (T_ - 1 - s) : s;
        float4 x = buf[s & 3];
        if (s + 4 < T_) buf[s & 3] = xsrc[idx + (long long)(s + 4) * step];
        const int p = s & 1;
        ulonglong2 hA = *(const ulonglong2*)&hsm[p][e][0];
        ulonglong2 hB = *(const ulonglong2*)&hsm[p][e][4];

        float gi = dot8(hA, hB, wi0, wi1, x.x);
        float gf = dot8(hA, hB, wf0, wf1, x.y);
        float gg = dot8(hA, hB, wg0, wg1, x.z);
        float go = dot8(hA, hB, wo0, wo1, x.w);

        float ii = sigm_hw(gi), ff = sigm_hw(gf);
        float g2 = tanh_hw(gg), oo = sigm_hw(go);
        cu = __fmaf_rn(ff, cu, ii * g2);
        float hu = oo * tanh_hw(cu);
        hsm[p ^ 1][e][u] = hu;
        __syncwarp();
        hp0[(size_t)tt * (B_ * 16)] = hu;
    }
}

// ---------------- K3: ptr-LSTM input projection (gate-interleaved output) -------
__global__ void __launch_bounds__(256) zproj_kernel(
    const float* __restrict__ Wihp, const float* __restrict__ bip,
    const float* __restrict__ bhp)
{
    __shared__ float W[64][16];
    __shared__ float bias[64];
    const int tid = threadIdx.x;
    #pragma unroll
    for (int i = tid; i < 1024; i += 256) {
        int n = i >> 4, k = i & 15;
        int u = n >> 2, g = n & 3;
        W[n][k] = Wihp[(g * 16 + u) * 16 + k];
    }
    if (tid < 64) {
        int u = tid >> 2, g = tid & 3;
        int r = g * 16 + u;
        bias[tid] = bip[r] + bhp[r];
    }
    __syncthreads();

    size_t r = (size_t)blockIdx.x * 256 + tid;
    const float4* h4 = (const float4*)(g_h + r * 16);
    float4 a0 = h4[0], a1 = h4[1], a2 = h4[2], a3 = h4[3];
    float hr[16] = {a0.x, a0.y, a0.z, a0.w, a1.x, a1.y, a1.z, a1.w,
                    a2.x, a2.y, a2.z, a2.w, a3.x, a3.y, a3.z, a3.w};
    float* out = g_zproj + r * 64;
    #pragma unroll
    for (int g0 = 0; g0 < 64; g0 += 4) {
        float o[4];
        #pragma unroll
        for (int q = 0; q < 4; q++) {
            int g = g0 + q;
            float a = bias[g];
            #pragma unroll
            for (int k = 0; k < 16; k++) a = __fmaf_rn(W[g][k], hr[k], a);
            o[q] = a;
        }
        *(float4*)(out + g0) = make_float4(o[0], o[1], o[2], o[3]);
    }
}

// ---------------- K4: ptr LSTM scan (H=16) ----------------
__global__ void __launch_bounds__(64) lstm_ptr_kernel(const float* __restrict__ Whhp)
{
    __shared__ __align__(64) float hsm[2][4][16];
    const int tid = threadIdx.x;
    const int e = tid >> 4, u = tid & 15;
    const int b = blockIdx.x * 4 + e;

    ulonglong2 wi[4], wf4[4], wg4[4], wo4[4];
    {
        const ulonglong2* p;
        p = (const ulonglong2*)(Whhp + u * 16);
        wi[0] = p[0]; wi[1] = p[1]; wi[2] = p[2]; wi[3] = p[3];
        p = (const ulonglong2*)(Whhp + (16 + u) * 16);
        wf4[0] = p[0]; wf4[1] = p[1]; wf4[2] = p[2]; wf4[3] = p[3];
        p = (const ulonglong2*)(Whhp + (32 + u) * 16);
        wg4[0] = p[0]; wg4[1] = p[1]; wg4[2] = p[2]; wg4[3] = p[3];
        p = (const ulonglong2*)(Whhp + (48 + u) * 16);
        wo4[0] = p[0]; wo4[1] = p[1]; wo4[2] = p[2]; wo4[3] = p[3];
    }

    hsm[0][e][u] = 0.f;
    __syncthreads();
    float cu = 0.f;

    const float4* zsrc = (const float4*)g_zproj;
    const long long stride4 = (long long)B_ * 16;
    long long idx = (long long)b * 16 + u;
    float4 buf[4];
    #pragma unroll
    for (int p = 0; p < 4; p++) buf[p] = zsrc[idx + p * stride4];

    float* zp0 = g_z + (size_t)b * 16 + u;

    #pragma unroll 4
    for (int t = 0; t < T_; t++) {
        float4 x = buf[t & 3];
        if (t + 4 < T_) buf[t & 3] = zsrc[idx + (long long)(t + 4) * stride4];
        const int p = t & 1;
        const ulonglong2* hr = (const ulonglong2*)&hsm[p][e][0];
        ulonglong2 hA = hr[0], hB = hr[1], hC = hr[2], hD = hr[3];

        float gi = dot16(hA, hB, hC, hD, wi[0], wi[1], wi[2], wi[3], x.x);
        float gf = dot16(hA, hB, hC, hD, wf4[0], wf4[1], wf4[2], wf4[3], x.y);
        float gg = dot16(hA, hB, hC, hD, wg4[0], wg4[1], wg4[2], wg4[3], x.z);
        float go = dot16(hA, hB, hC, hD, wo4[0], wo4[1], wo4[2], wo4[3], x.w);

        float ii = sigm_hw(gi), ff = sigm_hw(gf);
        float g2 = tanh_hw(gg), oo = sigm_hw(go);
        cu = __fmaf_rn(ff, cu, ii * g2);
        float hu = oo * tanh_hw(cu);
        hsm[p ^ 1][e][u] = hu;
        __syncwarp();
        zp0[(size_t)t * (B_ * 16)] = hu;
    }
}

// ---------------- K5: fused attention + output head, one CTA per t ----------------
// pass1: thread c computes column c of S once, stores exp(S) bf16 to g_eb,
//        colsum accumulated from the *rounded* values (consistent normalization).
//        z row is pre-scaled by log2(e) so exp(S) = ex2(dot).
// pass2: thread b reads its exp row back (LDG.128 = 8 exps), does only the
//        weighted AXPY into ctx. No S recompute, no second exp.
#define ATT_SMEM_FLOATS (8192 + 512 + 256 + 256 + 16)
__global__ void __launch_bounds__(512) attn_kernel(
    const float* __restrict__ W_h, const float* __restrict__ W_e,
    const float* __restrict__ W_v, float* __restrict__ out)
{
    extern __shared__ __align__(16) float sm[];
    float* hs   = sm;            // 512 x 16
    float* cinv = sm + 8192;     // 512
    float* whs  = sm + 8704;     // 16 x 16
    float* wes  = sm + 8960;     // 16 x 16
    float* wvs  = sm + 9216;     // 16

    const int tid = threadIdx.x;
    const int t = blockIdx.x;
    {
        const float4* hsrc = (const float4*)(g_h + (size_t)t * (B_ * 16));
        float4* hd = (float4*)hs;
        #pragma unroll
        for (int i = 0; i < 4; i++) hd[tid + i * 512] = hsrc[tid + i * 512];
    }
    if (tid < 256) { whs[tid] = W_h[tid]; wes[tid] = W_e[tid]; }
    if (tid < 16)  wvs[tid] = W_v[tid];
    __syncthreads();

    // ---- pass 1: thread c owns column c -> exp store + colsum ----
    {
        const float L2E = 1.44269504f;
        const float4* zg = (const float4*)(g_z + (size_t)t * (B_ * 16) + (size_t)tid * 16);
        float4 z0 = zg[0], z1 = zg[1], z2 = zg[2], z3 = zg[3];
        ull zq[8];
        zq[0] = pack2(z0.x * L2E, z0.y * L2E); zq[1] = pack2(z0.z * L2E, z0.w * L2E);
        zq[2] = pack2(z1.x * L2E, z1.y * L2E); zq[3] = pack2(z1.z * L2E, z1.w * L2E);
        zq[4] = pack2(z2.x * L2E, z2.y * L2E); zq[5] = pack2(z2.z * L2E, z2.w * L2E);
        zq[6] = pack2(z3.x * L2E, z3.y * L2E); zq[7] = pack2(z3.z * L2E, z3.w * L2E);

        __nv_bfloat16* ecol = g_eb + (size_t)t * B_ * B_ + tid;
        float colsum = 0.f;
        #pragma unroll 2
        for (int bb = 0; bb < B_; bb++) {
            const ulonglong2* hr = (const ulonglong2*)(hs + bb * 16);
            ulonglong2 hq0 = hr[0], hq1 = hr[1], hq2 = hr[2], hq3 = hr[3];
            ull aA = 0ULL, aB = 0ULL;
            aA = ffma2(hq0.x, zq[0], aA); aB = ffma2(hq0.y, zq[1], aB);
            aA = ffma2(hq1.x, zq[2], aA); aB = ffma2(hq1.y, zq[3], aB);
            aA = ffma2(hq2.x, zq[4], aA); aB = ffma2(hq2.y, zq[5], aB);
            aA = ffma2(hq3.x, zq[6], aA); aB = ffma2(hq3.y, zq[7], aB);
            float2 va = unpack2(aA), vb = unpack2(aB);
            float S = (va.x + va.y) + (vb.x + vb.y);
            float e = ex2(S);
            __nv_bfloat16 eb = __float2bfloat16(e);
            ecol[(size_t)bb * B_] = eb;
            colsum += __bfloat162float(eb);
        }
        cinv[tid] = __fdividef(1.f, colsum);
    }
    __syncthreads();   // orders g_eb writes + cinv for intra-CTA consumption

    // ---- pass 2 + output head: thread b owns row b ----
    {
        ull cacc[8];
        #pragma unroll
        for (int k = 0; k < 8; k++) cacc[k] = 0ULL;

        const __nv_bfloat16* erow = g_eb + (size_t)t * B_ * B_ + (size_t)tid * B_;
        for (int c0 = 0; c0 < B_; c0 += 8) {
            uint4 ev = *(const uint4*)(erow + c0);
            float4 ci0 = *(const float4*)(cinv + c0);
            float4 ci1 = *(const float4*)(cinv + c0 + 4);
            uint32_t uu[4] = {ev.x, ev.y, ev.z, ev.w};
            float cis[8] = {ci0.x, ci0.y, ci0.z, ci0.w, ci1.x, ci1.y, ci1.z, ci1.w};
            #pragma unroll
            for (int k = 0; k < 4; k++) {
                float e0 = __uint_as_float(uu[k] << 16);
                float e1 = __uint_as_float(uu[k] & 0xffff0000u);
                float w0 = e0 * cis[2 * k];
                float w1 = e1 * cis[2 * k + 1];
                {
                    ull w2 = pack2(w0, w0);
                    const ulonglong2* hc = (const ulonglong2*)(hs + (c0 + 2 * k) * 16);
                    ulonglong2 q0 = hc[0], q1 = hc[1], q2 = hc[2], q3 = hc[3];
                    cacc[0] = ffma2(q0.x, w2, cacc[0]); cacc[1] = ffma2(q0.y, w2, cacc[1]);
                    cacc[2] = ffma2(q1.x, w2, cacc[2]); cacc[3] = ffma2(q1.y, w2, cacc[3]);
                    cacc[4] = ffma2(q2.x, w2, cacc[4]); cacc[5] = ffma2(q2.y, w2, cacc[5]);
                    cacc[6] = ffma2(q3.x, w2, cacc[6]); cacc[7] = ffma2(q3.y, w2, cacc[7]);
                }
                {
                    ull w2 = pack2(w1, w1);
                    const ulonglong2* hc = (const ulonglong2*)(hs + (c0 + 2 * k + 1) * 16);
                    ulonglong2 q0 = hc[0], q1 = hc[1], q2 = hc[2], q3 = hc[3];
                    cacc[0] = ffma2(q0.x, w2, cacc[0]); cacc[1] = ffma2(q0.y, w2, cacc[1]);
                    cacc[2] = ffma2(q1.x, w2, cacc[2]); cacc[3] = ffma2(q1.y, w2, cacc[3]);
                    cacc[4] = ffma2(q2.x, w2, cacc[4]); cacc[5] = ffma2(q2.y, w2, cacc[5]);
                    cacc[6] = ffma2(q3.x, w2, cacc[6]); cacc[7] = ffma2(q3.y, w2, cacc[7]);
                }
            }
        }

        float ctxv[16], hbv[16];
        #pragma unroll
        for (int k = 0; k < 8; k++) {
            float2 v = unpack2(cacc[k]);
            ctxv[2 * k] = v.x; ctxv[2 * k + 1] = v.y;
        }
        {
            const float4* hb4 = (const float4*)(hs + tid * 16);
            float4 a0 = hb4[0], a1 = hb4[1], a2 = hb4[2], a3 = hb4[3];
            hbv[0] = a0.x;  hbv[1] = a0.y;  hbv[2] = a0.z;  hbv[3] = a0.w;
            hbv[4] = a1.x;  hbv[5] = a1.y;  hbv[6] = a1.z;  hbv[7] = a1.w;
            hbv[8] = a2.x;  hbv[9] = a2.y;  hbv[10] = a2.z; hbv[11] = a2.w;
            hbv[12] = a3.x; hbv[13] = a3.y; hbv[14] = a3.z; hbv[15] = a3.w;
        }
        float pacc = 0.f;
        #pragma unroll
        for (int d = 0; d < 16; d++) {
            float a = 0.f;
            #pragma unroll
            for (int k = 0; k < 16; k++) a = __fmaf_rn(whs[d * 16 + k], hbv[k], a);
            #pragma unroll
            for (int k = 0; k < 16; k++) a = __fmaf_rn(wes[d * 16 + k], ctxv[k], a);
            float ud = tanh_hw(a);
            pacc = __fmaf_rn(ud, wvs[d], pacc);
        }
        out[(size_t)t * B_ + tid] = sigm_hw(pacc);
    }
}

// ---------------- launch ----------------
extern "C" void kernel_launch(void* const* d_in, const int* in_sizes, int n_in,
                              void* d_out, int out_size)
{
    (void)in_sizes; (void)n_in; (void)out_size;
    const float* X     = (const float*)d_in[0];
    const float* Wih_f = (const float*)d_in[1];
    const float* Whh_f = (const float*)d_in[2];
    const float* bih_f = (const float*)d_in[3];
    const float* bhh_f = (const float*)d_in[4];
    const float* Wih_b = (const float*)d_in[5];
    const float* Whh_b = (const float*)d_in[6];
    const float* bih_b = (const float*)d_in[7];
    const float* bhh_b = (const float*)d_in[8];
    const float* Wih_p = (const float*)d_in[9];
    const float* Whh_p = (const float*)d_in[10];
    const float* bih_p = (const float*)d_in[11];
    const float* bhh_p = (const float*)d_in[12];
    const float* W_h   = (const float*)d_in[13];
    const float* W_e   = (const float*)d_in[14];
    const float* W_v   = (const float*)d_in[15];
    float* out = (float*)d_out;

    cudaFuncSetAttribute(proj_mma_kernel, cudaFuncAttributeMaxDynamicSharedMemorySize, PROJ_SMEM);
    proj_mma_kernel<<<R_ / 128, 256, PROJ_SMEM>>>(X, Wih_f, Wih_b, bih_f, bhh_f, bih_b, bhh_b);

    lstm_bi_kernel<<<dim3(64, 2), 64>>>(Whh_f, Whh_b);
    zproj_kernel<<<256, 256>>>(Wih_p, bih_p, bhh_p);
    lstm_ptr_kernel<<<128, 64>>>(Whh_p);

    const int att_smem = ATT_SMEM_FLOATS * (int)sizeof(float);  // ~37 KB
    cudaFuncSetAttribute(attn_kernel, cudaFuncAttributeMaxDynamicSharedMemorySize, att_smem);
    attn_kernel<<<128, 512, att_smem>>>(W_h, W_e, W_v, out);
}